// round 14
// baseline (speedup 1.0000x reference)
#include <cuda_runtime.h>
#include <math.h>
#include <stdint.h>

// ---------------- problem constants ----------------
#define N_NODES 50000
#define N_REL   50
#define N_BASES 30
#define NSEG    (N_NODES * N_REL)
#define MAXE    1100000
#define SCAN_CHUNK 2048
#define NB2 ((NSEG + SCAN_CHUNK - 1) / SCAN_CHUNK)
#define FULLM 0xffffffffu

// ---------------- static device scratch (zero-initialized at load) ----------------
__device__ int d_cnt[NSEG];
__device__ int d_off[NSEG + 1];
__device__ int d_cpt[NSEG + 1];
__device__ int d_cur[NSEG];
__device__ int d_coff[MAXE + 2];
__device__ int d_cdst[MAXE];
__device__ int d_srcn[MAXE];
__device__ unsigned long long d_agg[NB2];
__device__ unsigned long long d_incl[NB2];
__device__ int d_stat[NB2];
__device__ int d_bidc;
__device__ float d_W0[N_REL * 64 * 64];   // fragment-order n=64 (see k_prep)
__device__ float d_W1[N_REL * 64 * 64];   // fragment-order n=64
__device__ float d_W2[N_REL * 64 * 8];    // fragment-order n=8
__device__ float d_msg[N_NODES * 64];
__device__ float d_hA[N_NODES * 64];
__device__ float d_hB[N_NODES * 64];

__device__ __forceinline__ float tf32r(float v) {
    uint32_t u;
    asm("cvt.rna.tf32.f32 %0, %1;" : "=r"(u) : "f"(v));
    return __uint_as_float(u);
}
__device__ __forceinline__ void red2(float* p, float a, float b) {
    asm volatile("red.global.add.v2.f32 [%0], {%1, %2};" :: "l"(p), "f"(a), "f"(b) : "memory");
}

// ---------------- fused prep: edge histogram + W precomputes ----------------
// W0/W1 in MMA B-fragment order (n=64):
//   fi in [0,4096): s=fi&3, lane=(fi>>2)&31, jp=(fi>>7)&3, kk=fi>>9
//   j=2*jp+(s>>1), hb=s&1, q=lane&3, g=lane>>2; k=kk*8+q+hb*4, o=j*8+g -> W[r][k][o]
// W2 in MMA B-fragment order (n=8):
//   fi in [0,512): s=fi&1, lane=(fi>>1)&31, kk=fi>>6
//   q=lane&3, g=lane>>2; k=kk*8+q+s*4, o=g -> W[r][k][o]
__global__ void k_prep(const int* __restrict__ et, const int* __restrict__ dst, int E,
                       const float* __restrict__ b0, const float* __restrict__ c0,
                       const float* __restrict__ b1, const float* __restrict__ c1,
                       const float* __restrict__ b2, const float* __restrict__ c2) {
    int i = blockIdx.x * blockDim.x + threadIdx.x;
    if (i < E) atomicAdd(&d_cnt[et[i] * N_NODES + dst[i]], 1);
    if (i < N_REL * 64 * 64) {
        int r = i >> 12, fi = i & 4095;
        int s = fi & 3, lane = (fi >> 2) & 31, jp = (fi >> 7) & 3, kk = fi >> 9;
        int j = 2 * jp + (s >> 1);
        int hb = s & 1;
        int q = lane & 3, g = lane >> 2;
        int k = kk * 8 + q + hb * 4;
        int o = j * 8 + g;
        int ko = k * 64 + o;
        float a0 = 0.f, a1 = 0.f;
#pragma unroll 6
        for (int b = 0; b < N_BASES; b++) {
            a0 += c0[r * N_BASES + b] * b0[b * 4096 + ko];
            a1 += c1[r * N_BASES + b] * b1[b * 4096 + ko];
        }
        d_W0[i] = tf32r(a0);
        d_W1[i] = tf32r(a1);
    }
    if (i < N_REL * 64 * 8) {
        int r = i >> 9, fi = i & 511;
        int s = fi & 1, lane = (fi >> 1) & 31, kk = fi >> 6;
        int q = lane & 3, g = lane >> 2;
        int ko = (kk * 8 + q + s * 4) * 8 + g;
        float a2 = 0.f;
#pragma unroll 6
        for (int b = 0; b < N_BASES; b++)
            a2 += c2[r * N_BASES + b] * b2[b * 512 + ko];
        d_W2[i] = tf32r(a2);
    }
}

// single-pass decoupled-lookback scan of (cnt, cnt>0)
__global__ void __launch_bounds__(256) k_scan() {
    __shared__ int sbid;
    __shared__ unsigned long long sexcl;
    __shared__ int ssum[256], sflg[256];
    int t = threadIdx.x;
    if (t == 0) sbid = atomicAdd(&d_bidc, 1);
    __syncthreads();
    int bid = sbid;
    int base = bid * SCAN_CHUNK + t * 8;
    int v[8], f[8];
    int run1 = 0, run2 = 0;
#pragma unroll
    for (int j = 0; j < 8; j++) {
        int idx = base + j;
        int c = (idx < NSEG) ? d_cnt[idx] : 0;
        v[j] = run1; f[j] = run2;
        run1 += c; run2 += (c > 0);
    }
    ssum[t] = run1; sflg[t] = run2;
    __syncthreads();
    for (int d = 1; d < 256; d <<= 1) {
        int a = 0, b = 0;
        if (t >= d) { a = ssum[t - d]; b = sflg[t - d]; }
        __syncthreads();
        if (t >= d) { ssum[t] += a; sflg[t] += b; }
        __syncthreads();
    }
    unsigned long long blockAgg =
        ((unsigned long long)(unsigned)ssum[255] << 32) | (unsigned)sflg[255];
    if (t == 0) {
        *((volatile unsigned long long*)&d_agg[bid]) = blockAgg;
        __threadfence();
        *((volatile int*)&d_stat[bid]) = 1;
    }
    if (t < 32) {
        unsigned long long excl = 0;
        int p = bid - 1;
        while (p >= 0) {
            int pi = p - t;
            int st;
            do {
                st = (pi >= 0) ? *((volatile int*)&d_stat[pi]) : 2;
            } while (__any_sync(FULLM, st == 0));
            unsigned m2 = __ballot_sync(FULLM, pi >= 0 && st == 2);
            if (m2) {
                int lead = __ffs(m2) - 1;
                unsigned long long vv = 0ull;
                if (pi >= 0) {
                    if (t < lead)       vv = *((volatile unsigned long long*)&d_agg[pi]);
                    else if (t == lead) vv = *((volatile unsigned long long*)&d_incl[pi]);
                }
                for (int o = 16; o > 0; o >>= 1) vv += __shfl_down_sync(FULLM, vv, o);
                excl += __shfl_sync(FULLM, vv, 0);
                break;
            } else {
                unsigned long long vv =
                    (pi >= 0) ? *((volatile unsigned long long*)&d_agg[pi]) : 0ull;
                for (int o = 16; o > 0; o >>= 1) vv += __shfl_down_sync(FULLM, vv, o);
                excl += __shfl_sync(FULLM, vv, 0);
                p -= 32;
            }
        }
        if (t == 0) {
            sexcl = excl;
            *((volatile unsigned long long*)&d_incl[bid]) = excl + blockAgg;
            __threadfence();
            *((volatile int*)&d_stat[bid]) = 2;
        }
    }
    __syncthreads();
    int exS = (int)(sexcl >> 32), exF = (int)(sexcl & 0xffffffffu);
    int ts = exS + ssum[t] - run1;
    int tf = exF + sflg[t] - run2;
#pragma unroll
    for (int j = 0; j < 8; j++) {
        int idx = base + j;
        if (idx < NSEG) {
            int o = ts + v[j];
            d_off[idx] = o; d_cur[idx] = o; d_cpt[idx] = tf + f[j];
        }
    }
    if (bid == NB2 - 1 && t == 255) {
        d_off[NSEG] = exS + ssum[255];
        d_cpt[NSEG] = exF + sflg[255];
    }
}

// compact CSR + counting-sort scatter + state reset for next replay
__global__ void k_cscat(const int* __restrict__ et, const int* __restrict__ dst,
                        const int* __restrict__ src, int E) {
    int i = blockIdx.x * blockDim.x + threadIdx.x;
    if (i < NSEG) {
        int c = d_cnt[i];
        if (c > 0) {
            int cc = d_cpt[i];
            d_coff[cc] = d_off[i];
            d_cdst[cc] = i % N_NODES;
        }
        d_cnt[i] = 0;
    }
    if (i < E) {
        int key = et[i] * N_NODES + dst[i];
        int p = atomicAdd(&d_cur[key], 1);
        d_srcn[p] = src[i];
    }
    if (i < NB2) d_stat[i] = 0;
    if (i == 0) {
        d_bidc = 0;
        d_coff[d_cpt[NSEG]] = E;
    }
}

// ---------------- fused mean aggregation + tf32 MMA + red scatter ----------------
// Block = 128 compact segments of one relation.
// DOUT==64: 128 threads / 4 warps; warp owns 32 rows = 2 MMA tiles, B fragments
//   (LDG.128) reused for both tiles.
// DOUT==8:  256 threads / 8 warps; warp owns 16 rows = 1 tile; 8 MMAs with
//   fragment-order W2 via LDG.64 (no Ws smem, no SIMT LDS storm).
template <int DOUT>
__global__ void __launch_bounds__(DOUT == 64 ? 128 : 256)
k_agg(const float* __restrict__ x, const float* __restrict__ W) {
    constexpr int NTH = (DOUT == 64) ? 128 : 256;
    extern __shared__ float smem[];
    float* As = smem;                   // [128][68]
    int* sso = (int*)(As + 128 * 68);   // [129]
    int* sdn = sso + 129;               // [128]

    int r = blockIdx.y;
    int t = threadIdx.x, lane = t & 31, w = t >> 5;

    int baseC = d_cpt[r * N_NODES];
    int Cend  = d_cpt[(r + 1) * N_NODES];
    int cb    = baseC + blockIdx.x * 128;
    if (cb >= Cend) return;

    // segment metadata
    for (int i = t; i < 129; i += NTH) sso[i] = d_coff[min(cb + i, Cend)];
    for (int i = t; i < 128; i += NTH) sdn[i] = (cb + i < Cend) ? d_cdst[cb + i] : -1;
    __syncthreads();

    // ---- gather: 8 threads/segment, chunks of 4 unrolled passes ----
    {
        constexpr int SPP = NTH / 8;            // segments per pass
        constexpr int NCH = 128 / (4 * SPP);    // chunks
        int sub  = t & 7;
        int c0   = sub * 8;
        int segl = t >> 3;
#pragma unroll
        for (int ch = 0; ch < NCH; ch++) {
            int sb = ch * 4 * SPP;
            int e0[4], e1[4], s0[4];
#pragma unroll
            for (int p = 0; p < 4; p++) {
                int sg = sb + p * SPP + segl;
                e0[p] = sso[sg];
                e1[p] = sso[sg + 1];
            }
#pragma unroll
            for (int p = 0; p < 4; p++)
                s0[p] = (e1[p] > e0[p]) ? __ldg(&d_srcn[e0[p]]) : -1;
            float4 A0[4], A1[4];
#pragma unroll
            for (int p = 0; p < 4; p++) {
                if (s0[p] >= 0) {
                    const float4* xp = (const float4*)(x + s0[p] * 64 + c0);
                    A0[p] = __ldg(xp);
                    A1[p] = __ldg(xp + 1);
                } else {
                    A0[p] = make_float4(0.f, 0.f, 0.f, 0.f);
                    A1[p] = make_float4(0.f, 0.f, 0.f, 0.f);
                }
            }
#pragma unroll
            for (int p = 0; p < 4; p++) {
                for (int e = e0[p] + 1; e < e1[p]; e++) {
                    int s2 = __ldg(&d_srcn[e]);
                    const float4* xq = (const float4*)(x + s2 * 64 + c0);
                    float4 v0 = __ldg(xq), v1 = __ldg(xq + 1);
                    A0[p].x += v0.x; A0[p].y += v0.y; A0[p].z += v0.z; A0[p].w += v0.w;
                    A1[p].x += v1.x; A1[p].y += v1.y; A1[p].z += v1.z; A1[p].w += v1.w;
                }
            }
#pragma unroll
            for (int p = 0; p < 4; p++) {
                int cnt = e1[p] - e0[p];
                float inv = (cnt > 0) ? 1.f / (float)cnt : 0.f;
                int sg = sb + p * SPP + segl;
                float* dp = As + sg * 68 + c0;
                float4 o0, o1;
                o0.x = tf32r(A0[p].x * inv); o0.y = tf32r(A0[p].y * inv);
                o0.z = tf32r(A0[p].z * inv); o0.w = tf32r(A0[p].w * inv);
                o1.x = tf32r(A1[p].x * inv); o1.y = tf32r(A1[p].y * inv);
                o1.z = tf32r(A1[p].z * inv); o1.w = tf32r(A1[p].w * inv);
                *(float4*)dp = o0;
                *(float4*)(dp + 4) = o1;
            }
        }
    }
    __syncthreads();

    int g = lane >> 2, q = lane & 3;
    if (DOUT == 64) {
        const float* AL0 = As + (w * 32 + g) * 68;    // tile 0: rows g, g+8
        const float* AL8 = AL0 + 8 * 68;
        const float* AH0 = AL0 + 16 * 68;             // tile 1: rows g+16, g+24
        const float* AH8 = AL0 + 24 * 68;
        const float4* Wf = (const float4*)(W + r * 4096);
        float mac[2][8][4];
#pragma unroll
        for (int tt = 0; tt < 2; tt++)
#pragma unroll
            for (int j = 0; j < 8; j++)
#pragma unroll
                for (int i = 0; i < 4; i++) mac[tt][j][i] = 0.f;
#pragma unroll
        for (int kk = 0; kk < 8; kk++) {
            int k0 = kk * 8;
            uint32_t L0 = __float_as_uint(AL0[k0 + q]);
            uint32_t L1 = __float_as_uint(AL8[k0 + q]);
            uint32_t L2 = __float_as_uint(AL0[k0 + q + 4]);
            uint32_t L3 = __float_as_uint(AL8[k0 + q + 4]);
            uint32_t H0 = __float_as_uint(AH0[k0 + q]);
            uint32_t H1 = __float_as_uint(AH8[k0 + q]);
            uint32_t H2 = __float_as_uint(AH0[k0 + q + 4]);
            uint32_t H3 = __float_as_uint(AH8[k0 + q + 4]);
#pragma unroll
            for (int jp = 0; jp < 4; jp++) {
                float4 bf = __ldg(&Wf[(kk * 4 + jp) * 32 + lane]);
                uint32_t B0 = __float_as_uint(bf.x);
                uint32_t B1 = __float_as_uint(bf.y);
                uint32_t B2 = __float_as_uint(bf.z);
                uint32_t B3 = __float_as_uint(bf.w);
                asm volatile(
                    "mma.sync.aligned.m16n8k8.row.col.f32.tf32.tf32.f32 "
                    "{%0,%1,%2,%3}, {%4,%5,%6,%7}, {%8,%9}, {%0,%1,%2,%3};"
                    : "+f"(mac[0][2*jp][0]), "+f"(mac[0][2*jp][1]),
                      "+f"(mac[0][2*jp][2]), "+f"(mac[0][2*jp][3])
                    : "r"(L0), "r"(L1), "r"(L2), "r"(L3), "r"(B0), "r"(B1));
                asm volatile(
                    "mma.sync.aligned.m16n8k8.row.col.f32.tf32.tf32.f32 "
                    "{%0,%1,%2,%3}, {%4,%5,%6,%7}, {%8,%9}, {%0,%1,%2,%3};"
                    : "+f"(mac[0][2*jp+1][0]), "+f"(mac[0][2*jp+1][1]),
                      "+f"(mac[0][2*jp+1][2]), "+f"(mac[0][2*jp+1][3])
                    : "r"(L0), "r"(L1), "r"(L2), "r"(L3), "r"(B2), "r"(B3));
                asm volatile(
                    "mma.sync.aligned.m16n8k8.row.col.f32.tf32.tf32.f32 "
                    "{%0,%1,%2,%3}, {%4,%5,%6,%7}, {%8,%9}, {%0,%1,%2,%3};"
                    : "+f"(mac[1][2*jp][0]), "+f"(mac[1][2*jp][1]),
                      "+f"(mac[1][2*jp][2]), "+f"(mac[1][2*jp][3])
                    : "r"(H0), "r"(H1), "r"(H2), "r"(H3), "r"(B0), "r"(B1));
                asm volatile(
                    "mma.sync.aligned.m16n8k8.row.col.f32.tf32.tf32.f32 "
                    "{%0,%1,%2,%3}, {%4,%5,%6,%7}, {%8,%9}, {%0,%1,%2,%3};"
                    : "+f"(mac[1][2*jp+1][0]), "+f"(mac[1][2*jp+1][1]),
                      "+f"(mac[1][2*jp+1][2]), "+f"(mac[1][2*jp+1][3])
                    : "r"(H0), "r"(H1), "r"(H2), "r"(H3), "r"(B2), "r"(B3));
            }
        }
#pragma unroll
        for (int tt = 0; tt < 2; tt++) {
            int dA = sdn[w * 32 + tt * 16 + g];
            int dB = sdn[w * 32 + tt * 16 + 8 + g];
#pragma unroll
            for (int j = 0; j < 8; j++) {
                int col = j * 8 + 2 * q;
                if (dA >= 0) red2(&d_msg[dA * 64 + col], mac[tt][j][0], mac[tt][j][1]);
                if (dB >= 0) red2(&d_msg[dB * 64 + col], mac[tt][j][2], mac[tt][j][3]);
            }
        }
    } else {
        // DOUT == 8 : one 16x8 MMA tile per warp, fragment-order W2 via LDG.64
        const float* Ar0 = As + (w * 16 + g) * 68;
        const float* Ar8 = Ar0 + 8 * 68;
        const float2* Wf = (const float2*)(W + r * 512);
        float mac[4] = {0.f, 0.f, 0.f, 0.f};
#pragma unroll
        for (int kk = 0; kk < 8; kk++) {
            int k0 = kk * 8;
            uint32_t A0 = __float_as_uint(Ar0[k0 + q]);
            uint32_t A1 = __float_as_uint(Ar8[k0 + q]);
            uint32_t A2 = __float_as_uint(Ar0[k0 + q + 4]);
            uint32_t A3 = __float_as_uint(Ar8[k0 + q + 4]);
            float2 bf = __ldg(&Wf[kk * 32 + lane]);
            uint32_t B0 = __float_as_uint(bf.x);
            uint32_t B1 = __float_as_uint(bf.y);
            asm volatile(
                "mma.sync.aligned.m16n8k8.row.col.f32.tf32.tf32.f32 "
                "{%0,%1,%2,%3}, {%4,%5,%6,%7}, {%8,%9}, {%0,%1,%2,%3};"
                : "+f"(mac[0]), "+f"(mac[1]), "+f"(mac[2]), "+f"(mac[3])
                : "r"(A0), "r"(A1), "r"(A2), "r"(A3), "r"(B0), "r"(B1));
        }
        int dA = sdn[w * 16 + g];
        int dB = sdn[w * 16 + 8 + g];
        int col = 2 * q;
        if (dA >= 0) red2(&d_msg[dA * 8 + col], mac[0], mac[1]);
        if (dB >= 0) red2(&d_msg[dB * 8 + col], mac[2], mac[3]);
    }
}

// epilogue: h = relu(msg + x@root + bias); re-zero msg.
// Thread computes 4 consecutive outputs of one node; all loads float4.
__global__ void k_rootrelu(const float* __restrict__ x, const float* __restrict__ root,
                           const float* __restrict__ bias, float* __restrict__ h) {
    int idx = blockIdx.x * blockDim.x + threadIdx.x;
    if (idx >= N_NODES * 16) return;
    int n = idx >> 4, og = idx & 15;
    const float4* x4 = (const float4*)(x + n * 64);
    const float4* r4 = (const float4*)root;     // [64][16] float4 view
    float4 acc = __ldg((const float4*)bias + og);
    float4* mp = (float4*)(d_msg + n * 64 + og * 4);
    float4 m = *mp;
    acc.x += m.x; acc.y += m.y; acc.z += m.z; acc.w += m.w;
    *mp = make_float4(0.f, 0.f, 0.f, 0.f);
#pragma unroll
    for (int i4 = 0; i4 < 16; i4++) {
        float4 xv = __ldg(&x4[i4]);
        float4 r0 = __ldg(&r4[(i4 * 4 + 0) * 16 + og]);
        float4 r1 = __ldg(&r4[(i4 * 4 + 1) * 16 + og]);
        float4 r2 = __ldg(&r4[(i4 * 4 + 2) * 16 + og]);
        float4 r3 = __ldg(&r4[(i4 * 4 + 3) * 16 + og]);
        acc.x += xv.x * r0.x + xv.y * r1.x + xv.z * r2.x + xv.w * r3.x;
        acc.y += xv.x * r0.y + xv.y * r1.y + xv.z * r2.y + xv.w * r3.y;
        acc.z += xv.x * r0.z + xv.y * r1.z + xv.z * r2.z + xv.w * r3.z;
        acc.w += xv.x * r0.w + xv.y * r1.w + xv.z * r2.w + xv.w * r3.w;
    }
    float4 out;
    out.x = acc.x > 0.f ? acc.x : 0.f;
    out.y = acc.y > 0.f ? acc.y : 0.f;
    out.z = acc.z > 0.f ? acc.z : 0.f;
    out.w = acc.w > 0.f ? acc.w : 0.f;
    *(float4*)(h + n * 64 + og * 4) = out;
}

// final epilogue: out = log_softmax(msg + x@root + bias); re-zero msg slice
__global__ void k_rootlsm(const float* __restrict__ x, const float* __restrict__ root,
                          const float* __restrict__ bias, float* __restrict__ out) {
    int n = blockIdx.x * blockDim.x + threadIdx.x;
    if (n >= N_NODES) return;
    float4 vlo = *(float4*)(d_msg + n * 8);
    float4 vhi = *(float4*)(d_msg + n * 8 + 4);
    float4 blo = __ldg((const float4*)bias);
    float4 bhi = __ldg((const float4*)bias + 1);
    vlo.x += blo.x; vlo.y += blo.y; vlo.z += blo.z; vlo.w += blo.w;
    vhi.x += bhi.x; vhi.y += bhi.y; vhi.z += bhi.z; vhi.w += bhi.w;
    *(float4*)(d_msg + n * 8) = make_float4(0.f, 0.f, 0.f, 0.f);
    *(float4*)(d_msg + n * 8 + 4) = make_float4(0.f, 0.f, 0.f, 0.f);
    const float4* x4 = (const float4*)(x + n * 64);
    const float4* r4 = (const float4*)root;   // [64][2] float4 view
#pragma unroll
    for (int i4 = 0; i4 < 16; i4++) {
        float4 xv = __ldg(&x4[i4]);
        float xs[4] = {xv.x, xv.y, xv.z, xv.w};
#pragma unroll
        for (int j = 0; j < 4; j++) {
            int i = i4 * 4 + j;
            float4 a = __ldg(&r4[i * 2]);
            float4 b = __ldg(&r4[i * 2 + 1]);
            vlo.x += xs[j] * a.x; vlo.y += xs[j] * a.y;
            vlo.z += xs[j] * a.z; vlo.w += xs[j] * a.w;
            vhi.x += xs[j] * b.x; vhi.y += xs[j] * b.y;
            vhi.z += xs[j] * b.z; vhi.w += xs[j] * b.w;
        }
    }
    float v[8] = {vlo.x, vlo.y, vlo.z, vlo.w, vhi.x, vhi.y, vhi.z, vhi.w};
    float m = -1e30f;
#pragma unroll
    for (int c = 0; c < 8; c++) m = fmaxf(m, v[c]);
    float s = 0.f;
#pragma unroll
    for (int c = 0; c < 8; c++) s += expf(v[c] - m);
    float ls = logf(s) + m;
#pragma unroll
    for (int c = 0; c < 8; c++) out[n * 8 + c] = v[c] - ls;
}

// ---------------- launch ----------------
extern "C" void kernel_launch(void* const* d_in, const int* in_sizes, int n_in,
                              void* d_out, int out_size) {
    const float* x0 = (const float*)d_in[0];
    const int* ei = (const int*)d_in[1];
    const int* et = (const int*)d_in[2];
    int E = in_sizes[2];
    const int* src = ei;
    const int* dst = ei + E;

    void *pA, *pB, *pW0, *pW1, *pW2;
    cudaGetSymbolAddress(&pA, d_hA);
    cudaGetSymbolAddress(&pB, d_hB);
    cudaGetSymbolAddress(&pW0, d_W0);
    cudaGetSymbolAddress(&pW1, d_W1);
    cudaGetSymbolAddress(&pW2, d_W2);
    float* hA = (float*)pA;
    float* hB = (float*)pB;

    const int SMEM = (128 * 68) * 4 + 129 * 4 + 128 * 4;
    cudaFuncSetAttribute(k_agg<64>, cudaFuncAttributeMaxDynamicSharedMemorySize, SMEM);
    cudaFuncSetAttribute(k_agg<8>,  cudaFuncAttributeMaxDynamicSharedMemorySize, SMEM);

    dim3 grid((N_NODES + 127) / 128, N_REL);

    // 1: prep;  2: scan;  3: compact+scatter+reset;  4: k_agg<64>  <- ncu slot
    k_prep<<<(E + 255) / 256, 256>>>(et, dst, E,
        (const float*)d_in[3], (const float*)d_in[4],
        (const float*)d_in[7], (const float*)d_in[8],
        (const float*)d_in[11], (const float*)d_in[12]);
    k_scan<<<NB2, 256>>>();
    k_cscat<<<(NSEG + 255) / 256, 256>>>(et, dst, src, E);

    k_agg<64><<<grid, 128, SMEM>>>(x0, (const float*)pW0);
    k_rootrelu<<<(N_NODES * 16 + 255) / 256, 256>>>(x0, (const float*)d_in[5],
                                                    (const float*)d_in[6], hA);

    k_agg<64><<<grid, 128, SMEM>>>(hA, (const float*)pW1);
    k_rootrelu<<<(N_NODES * 16 + 255) / 256, 256>>>(hA, (const float*)d_in[9],
                                                    (const float*)d_in[10], hB);

    k_agg<8><<<grid, 256, SMEM>>>(hB, (const float*)pW2);
    k_rootlsm<<<(N_NODES + 255) / 256, 256>>>(hB, (const float*)d_in[13], (const float*)d_in[14],
                                              (float*)d_out);
}

// round 15
// speedup vs baseline: 1.4203x; 1.4203x over previous
#include <cuda_runtime.h>
#include <math.h>
#include <stdint.h>

// ---------------- problem constants ----------------
#define N_NODES 50000
#define N_REL   50
#define N_BASES 30
#define NSEG    (N_NODES * N_REL)
#define MAXE    1100000
#define SCAN_CHUNK 2048
#define NB2 ((NSEG + SCAN_CHUNK - 1) / SCAN_CHUNK)
#define FULLM 0xffffffffu

// ---------------- static device scratch (zero-initialized at load) ----------------
__device__ int d_cnt[NSEG];
__device__ int d_off[NSEG + 1];
__device__ int d_cpt[NSEG + 1];
__device__ int d_cur[NSEG];
__device__ int d_coff[MAXE + 2];
__device__ int d_cdst[MAXE];
__device__ int d_srcn[MAXE];
__device__ unsigned long long d_agg[NB2];
__device__ unsigned long long d_incl[NB2];
__device__ int d_stat[NB2];
__device__ int d_bidc;
__device__ float d_W0[N_REL * 64 * 64];   // fragment-order n=64 (see k_prep)
__device__ float d_W1[N_REL * 64 * 64];   // fragment-order n=64
__device__ float d_W2[N_REL * 64 * 8];    // k-major (SIMT path)
__device__ float d_msg[N_NODES * 64];
__device__ float d_hA[N_NODES * 64];
__device__ float d_hB[N_NODES * 64];

__device__ __forceinline__ float tf32r(float v) {
    uint32_t u;
    asm("cvt.rna.tf32.f32 %0, %1;" : "=r"(u) : "f"(v));
    return __uint_as_float(u);
}
__device__ __forceinline__ void red2(float* p, float a, float b) {
    asm volatile("red.global.add.v2.f32 [%0], {%1, %2};" :: "l"(p), "f"(a), "f"(b) : "memory");
}
__device__ __forceinline__ void red4(float* p, float a, float b, float c, float d) {
    asm volatile("red.global.add.v4.f32 [%0], {%1, %2, %3, %4};"
                 :: "l"(p), "f"(a), "f"(b), "f"(c), "f"(d) : "memory");
}

// ---------------- fused prep: edge histogram + W precomputes ----------------
// W0/W1 in MMA B-fragment order (n=64):
//   fi in [0,4096): s=fi&3, lane=(fi>>2)&31, jp=(fi>>7)&3, kk=fi>>9
//   j=2*jp+(s>>1), hb=s&1, q=lane&3, g=lane>>2; k=kk*8+q+hb*4, o=j*8+g -> W[r][k][o]
// W2 k-major (SIMT epilogue).
__global__ void k_prep(const int* __restrict__ et, const int* __restrict__ dst, int E,
                       const float* __restrict__ b0, const float* __restrict__ c0,
                       const float* __restrict__ b1, const float* __restrict__ c1,
                       const float* __restrict__ b2, const float* __restrict__ c2) {
    int i = blockIdx.x * blockDim.x + threadIdx.x;
    if (i < E) atomicAdd(&d_cnt[et[i] * N_NODES + dst[i]], 1);
    if (i < N_REL * 64 * 64) {
        int r = i >> 12, fi = i & 4095;
        int s = fi & 3, lane = (fi >> 2) & 31, jp = (fi >> 7) & 3, kk = fi >> 9;
        int j = 2 * jp + (s >> 1);
        int hb = s & 1;
        int q = lane & 3, g = lane >> 2;
        int k = kk * 8 + q + hb * 4;
        int o = j * 8 + g;
        int ko = k * 64 + o;
        float a0 = 0.f, a1 = 0.f;
#pragma unroll 6
        for (int b = 0; b < N_BASES; b++) {
            a0 += c0[r * N_BASES + b] * b0[b * 4096 + ko];
            a1 += c1[r * N_BASES + b] * b1[b * 4096 + ko];
        }
        d_W0[i] = tf32r(a0);
        d_W1[i] = tf32r(a1);
    }
    if (i < N_REL * 64 * 8) {
        int r = i >> 9, ko = i & 511;
        float a2 = 0.f;
#pragma unroll 6
        for (int b = 0; b < N_BASES; b++)
            a2 += c2[r * N_BASES + b] * b2[b * 512 + ko];
        d_W2[i] = a2;
    }
}

// single-pass decoupled-lookback scan of (cnt, cnt>0)
__global__ void __launch_bounds__(256) k_scan() {
    __shared__ int sbid;
    __shared__ unsigned long long sexcl;
    __shared__ int ssum[256], sflg[256];
    int t = threadIdx.x;
    if (t == 0) sbid = atomicAdd(&d_bidc, 1);
    __syncthreads();
    int bid = sbid;
    int base = bid * SCAN_CHUNK + t * 8;
    int v[8], f[8];
    int run1 = 0, run2 = 0;
#pragma unroll
    for (int j = 0; j < 8; j++) {
        int idx = base + j;
        int c = (idx < NSEG) ? d_cnt[idx] : 0;
        v[j] = run1; f[j] = run2;
        run1 += c; run2 += (c > 0);
    }
    ssum[t] = run1; sflg[t] = run2;
    __syncthreads();
    for (int d = 1; d < 256; d <<= 1) {
        int a = 0, b = 0;
        if (t >= d) { a = ssum[t - d]; b = sflg[t - d]; }
        __syncthreads();
        if (t >= d) { ssum[t] += a; sflg[t] += b; }
        __syncthreads();
    }
    unsigned long long blockAgg =
        ((unsigned long long)(unsigned)ssum[255] << 32) | (unsigned)sflg[255];
    if (t == 0) {
        *((volatile unsigned long long*)&d_agg[bid]) = blockAgg;
        __threadfence();
        *((volatile int*)&d_stat[bid]) = 1;
    }
    if (t < 32) {
        unsigned long long excl = 0;
        int p = bid - 1;
        while (p >= 0) {
            int pi = p - t;
            int st;
            do {
                st = (pi >= 0) ? *((volatile int*)&d_stat[pi]) : 2;
            } while (__any_sync(FULLM, st == 0));
            unsigned m2 = __ballot_sync(FULLM, pi >= 0 && st == 2);
            if (m2) {
                int lead = __ffs(m2) - 1;
                unsigned long long vv = 0ull;
                if (pi >= 0) {
                    if (t < lead)       vv = *((volatile unsigned long long*)&d_agg[pi]);
                    else if (t == lead) vv = *((volatile unsigned long long*)&d_incl[pi]);
                }
                for (int o = 16; o > 0; o >>= 1) vv += __shfl_down_sync(FULLM, vv, o);
                excl += __shfl_sync(FULLM, vv, 0);
                break;
            } else {
                unsigned long long vv =
                    (pi >= 0) ? *((volatile unsigned long long*)&d_agg[pi]) : 0ull;
                for (int o = 16; o > 0; o >>= 1) vv += __shfl_down_sync(FULLM, vv, o);
                excl += __shfl_sync(FULLM, vv, 0);
                p -= 32;
            }
        }
        if (t == 0) {
            sexcl = excl;
            *((volatile unsigned long long*)&d_incl[bid]) = excl + blockAgg;
            __threadfence();
            *((volatile int*)&d_stat[bid]) = 2;
        }
    }
    __syncthreads();
    int exS = (int)(sexcl >> 32), exF = (int)(sexcl & 0xffffffffu);
    int ts = exS + ssum[t] - run1;
    int tf = exF + sflg[t] - run2;
#pragma unroll
    for (int j = 0; j < 8; j++) {
        int idx = base + j;
        if (idx < NSEG) {
            int o = ts + v[j];
            d_off[idx] = o; d_cur[idx] = o; d_cpt[idx] = tf + f[j];
        }
    }
    if (bid == NB2 - 1 && t == 255) {
        d_off[NSEG] = exS + ssum[255];
        d_cpt[NSEG] = exF + sflg[255];
    }
}

// compact CSR + counting-sort scatter + state reset for next replay
__global__ void k_cscat(const int* __restrict__ et, const int* __restrict__ dst,
                        const int* __restrict__ src, int E) {
    int i = blockIdx.x * blockDim.x + threadIdx.x;
    if (i < NSEG) {
        int c = d_cnt[i];
        if (c > 0) {
            int cc = d_cpt[i];
            d_coff[cc] = d_off[i];
            d_cdst[cc] = i % N_NODES;
        }
        d_cnt[i] = 0;
    }
    if (i < E) {
        int key = et[i] * N_NODES + dst[i];
        int p = atomicAdd(&d_cur[key], 1);
        d_srcn[p] = src[i];
    }
    if (i < NB2) d_stat[i] = 0;
    if (i == 0) {
        d_bidc = 0;
        d_coff[d_cpt[NSEG]] = E;
    }
}

// ---------------- fused mean aggregation + tf32 MMA + red scatter ----------------
// Block = 128 compact segments of one relation.
// DOUT==64: 128 threads / 4 warps; warp owns 32 rows = 2 MMA tiles (B reuse).
// DOUT==8:  256 threads, SIMT epilogue with Ws smem (proven R13 shape).
template <int DOUT>
__global__ void __launch_bounds__(DOUT == 64 ? 128 : 256)
k_agg(const float* __restrict__ x, const float* __restrict__ W) {
    constexpr int NTH = (DOUT == 64) ? 128 : 256;
    extern __shared__ float smem[];
    float* Ws;   // only for DOUT==8
    float* As;
    if (DOUT == 8) { Ws = smem; As = smem + 64 * 8; }
    else           { Ws = nullptr; As = smem; }
    int* sso = (int*)(As + 128 * 68);   // [129]
    int* sdn = sso + 129;               // [128]

    int r = blockIdx.y;
    int t = threadIdx.x, lane = t & 31, w = t >> 5;

    int baseC = d_cpt[r * N_NODES];
    int Cend  = d_cpt[(r + 1) * N_NODES];
    int cb    = baseC + blockIdx.x * 128;
    if (cb >= Cend) return;

    if (DOUT == 8) {
        const float* Wr = W + r * 64 * 8;
        for (int i = t; i < 64 * 8; i += NTH) Ws[i] = Wr[i];
    }
    // segment metadata
    for (int i = t; i < 129; i += NTH) sso[i] = d_coff[min(cb + i, Cend)];
    for (int i = t; i < 128; i += NTH) sdn[i] = (cb + i < Cend) ? d_cdst[cb + i] : -1;
    __syncthreads();

    // ---- gather: 8 threads/segment, chunks of 4 unrolled passes ----
    {
        constexpr int SPP = NTH / 8;            // segments per pass
        constexpr int NCH = 128 / (4 * SPP);    // chunks
        int sub  = t & 7;
        int c0   = sub * 8;
        int segl = t >> 3;
#pragma unroll
        for (int ch = 0; ch < NCH; ch++) {
            int sb = ch * 4 * SPP;
            int e0[4], e1[4], s0[4];
#pragma unroll
            for (int p = 0; p < 4; p++) {
                int sg = sb + p * SPP + segl;
                e0[p] = sso[sg];
                e1[p] = sso[sg + 1];
            }
#pragma unroll
            for (int p = 0; p < 4; p++)
                s0[p] = (e1[p] > e0[p]) ? __ldg(&d_srcn[e0[p]]) : -1;
            float4 A0[4], A1[4];
#pragma unroll
            for (int p = 0; p < 4; p++) {
                if (s0[p] >= 0) {
                    const float4* xp = (const float4*)(x + s0[p] * 64 + c0);
                    A0[p] = __ldg(xp);
                    A1[p] = __ldg(xp + 1);
                } else {
                    A0[p] = make_float4(0.f, 0.f, 0.f, 0.f);
                    A1[p] = make_float4(0.f, 0.f, 0.f, 0.f);
                }
            }
#pragma unroll
            for (int p = 0; p < 4; p++) {
                for (int e = e0[p] + 1; e < e1[p]; e++) {
                    int s2 = __ldg(&d_srcn[e]);
                    const float4* xq = (const float4*)(x + s2 * 64 + c0);
                    float4 v0 = __ldg(xq), v1 = __ldg(xq + 1);
                    A0[p].x += v0.x; A0[p].y += v0.y; A0[p].z += v0.z; A0[p].w += v0.w;
                    A1[p].x += v1.x; A1[p].y += v1.y; A1[p].z += v1.z; A1[p].w += v1.w;
                }
            }
#pragma unroll
            for (int p = 0; p < 4; p++) {
                int cnt = e1[p] - e0[p];
                float inv = (cnt > 0) ? 1.f / (float)cnt : 0.f;
                int sg = sb + p * SPP + segl;
                float* dp = As + sg * 68 + c0;
                float4 o0, o1;
                o0.x = tf32r(A0[p].x * inv); o0.y = tf32r(A0[p].y * inv);
                o0.z = tf32r(A0[p].z * inv); o0.w = tf32r(A0[p].w * inv);
                o1.x = tf32r(A1[p].x * inv); o1.y = tf32r(A1[p].y * inv);
                o1.z = tf32r(A1[p].z * inv); o1.w = tf32r(A1[p].w * inv);
                *(float4*)dp = o0;
                *(float4*)(dp + 4) = o1;
            }
        }
    }
    __syncthreads();

    if (DOUT == 64) {
        int g = lane >> 2, q = lane & 3;
        const float* AL0 = As + (w * 32 + g) * 68;    // tile 0: rows g, g+8
        const float* AL8 = AL0 + 8 * 68;
        const float* AH0 = AL0 + 16 * 68;             // tile 1: rows g+16, g+24
        const float* AH8 = AL0 + 24 * 68;
        const float4* Wf = (const float4*)(W + r * 4096);
        float mac[2][8][4];
#pragma unroll
        for (int tt = 0; tt < 2; tt++)
#pragma unroll
            for (int j = 0; j < 8; j++)
#pragma unroll
                for (int i = 0; i < 4; i++) mac[tt][j][i] = 0.f;
#pragma unroll
        for (int kk = 0; kk < 8; kk++) {
            int k0 = kk * 8;
            uint32_t L0 = __float_as_uint(AL0[k0 + q]);
            uint32_t L1 = __float_as_uint(AL8[k0 + q]);
            uint32_t L2 = __float_as_uint(AL0[k0 + q + 4]);
            uint32_t L3 = __float_as_uint(AL8[k0 + q + 4]);
            uint32_t H0 = __float_as_uint(AH0[k0 + q]);
            uint32_t H1 = __float_as_uint(AH8[k0 + q]);
            uint32_t H2 = __float_as_uint(AH0[k0 + q + 4]);
            uint32_t H3 = __float_as_uint(AH8[k0 + q + 4]);
#pragma unroll
            for (int jp = 0; jp < 4; jp++) {
                float4 bf = __ldg(&Wf[(kk * 4 + jp) * 32 + lane]);
                uint32_t B0 = __float_as_uint(bf.x);
                uint32_t B1 = __float_as_uint(bf.y);
                uint32_t B2 = __float_as_uint(bf.z);
                uint32_t B3 = __float_as_uint(bf.w);
                asm volatile(
                    "mma.sync.aligned.m16n8k8.row.col.f32.tf32.tf32.f32 "
                    "{%0,%1,%2,%3}, {%4,%5,%6,%7}, {%8,%9}, {%0,%1,%2,%3};"
                    : "+f"(mac[0][2*jp][0]), "+f"(mac[0][2*jp][1]),
                      "+f"(mac[0][2*jp][2]), "+f"(mac[0][2*jp][3])
                    : "r"(L0), "r"(L1), "r"(L2), "r"(L3), "r"(B0), "r"(B1));
                asm volatile(
                    "mma.sync.aligned.m16n8k8.row.col.f32.tf32.tf32.f32 "
                    "{%0,%1,%2,%3}, {%4,%5,%6,%7}, {%8,%9}, {%0,%1,%2,%3};"
                    : "+f"(mac[0][2*jp+1][0]), "+f"(mac[0][2*jp+1][1]),
                      "+f"(mac[0][2*jp+1][2]), "+f"(mac[0][2*jp+1][3])
                    : "r"(L0), "r"(L1), "r"(L2), "r"(L3), "r"(B2), "r"(B3));
                asm volatile(
                    "mma.sync.aligned.m16n8k8.row.col.f32.tf32.tf32.f32 "
                    "{%0,%1,%2,%3}, {%4,%5,%6,%7}, {%8,%9}, {%0,%1,%2,%3};"
                    : "+f"(mac[1][2*jp][0]), "+f"(mac[1][2*jp][1]),
                      "+f"(mac[1][2*jp][2]), "+f"(mac[1][2*jp][3])
                    : "r"(H0), "r"(H1), "r"(H2), "r"(H3), "r"(B0), "r"(B1));
                asm volatile(
                    "mma.sync.aligned.m16n8k8.row.col.f32.tf32.tf32.f32 "
                    "{%0,%1,%2,%3}, {%4,%5,%6,%7}, {%8,%9}, {%0,%1,%2,%3};"
                    : "+f"(mac[1][2*jp+1][0]), "+f"(mac[1][2*jp+1][1]),
                      "+f"(mac[1][2*jp+1][2]), "+f"(mac[1][2*jp+1][3])
                    : "r"(H0), "r"(H1), "r"(H2), "r"(H3), "r"(B2), "r"(B3));
            }
        }
#pragma unroll
        for (int tt = 0; tt < 2; tt++) {
            int dA = sdn[w * 32 + tt * 16 + g];
            int dB = sdn[w * 32 + tt * 16 + 8 + g];
#pragma unroll
            for (int j = 0; j < 8; j++) {
                int col = j * 8 + 2 * q;
                if (dA >= 0) red2(&d_msg[dA * 64 + col], mac[tt][j][0], mac[tt][j][1]);
                if (dB >= 0) red2(&d_msg[dB * 64 + col], mac[tt][j][2], mac[tt][j][3]);
            }
        }
    } else {
        int row = t >> 1;
        int c0 = (t & 1) * 4;
        const float* Ar = As + row * 68;
        float s0 = 0.f, s1 = 0.f, s2 = 0.f, s3 = 0.f;
#pragma unroll
        for (int k = 0; k < 64; k++) {
            float a = Ar[k];
            float4 b = *(const float4*)&Ws[k * 8 + c0];
            s0 += a * b.x; s1 += a * b.y; s2 += a * b.z; s3 += a * b.w;
        }
        int dn = sdn[row];
        if (dn >= 0) red4(&d_msg[dn * 8 + c0], s0, s1, s2, s3);
    }
}

// epilogue: h = relu(msg + x@root + bias); re-zero msg.
// Thread computes 4 consecutive outputs of one node; all loads float4.
__global__ void k_rootrelu(const float* __restrict__ x, const float* __restrict__ root,
                           const float* __restrict__ bias, float* __restrict__ h) {
    int idx = blockIdx.x * blockDim.x + threadIdx.x;
    if (idx >= N_NODES * 16) return;
    int n = idx >> 4, og = idx & 15;
    const float4* x4 = (const float4*)(x + n * 64);
    const float4* r4 = (const float4*)root;     // [64][16] float4 view
    float4 acc = __ldg((const float4*)bias + og);
    float4* mp = (float4*)(d_msg + n * 64 + og * 4);
    float4 m = *mp;
    acc.x += m.x; acc.y += m.y; acc.z += m.z; acc.w += m.w;
    *mp = make_float4(0.f, 0.f, 0.f, 0.f);
#pragma unroll
    for (int i4 = 0; i4 < 16; i4++) {
        float4 xv = __ldg(&x4[i4]);
        float4 r0 = __ldg(&r4[(i4 * 4 + 0) * 16 + og]);
        float4 r1 = __ldg(&r4[(i4 * 4 + 1) * 16 + og]);
        float4 r2 = __ldg(&r4[(i4 * 4 + 2) * 16 + og]);
        float4 r3 = __ldg(&r4[(i4 * 4 + 3) * 16 + og]);
        acc.x += xv.x * r0.x + xv.y * r1.x + xv.z * r2.x + xv.w * r3.x;
        acc.y += xv.x * r0.y + xv.y * r1.y + xv.z * r2.y + xv.w * r3.y;
        acc.z += xv.x * r0.z + xv.y * r1.z + xv.z * r2.z + xv.w * r3.z;
        acc.w += xv.x * r0.w + xv.y * r1.w + xv.z * r2.w + xv.w * r3.w;
    }
    float4 out;
    out.x = acc.x > 0.f ? acc.x : 0.f;
    out.y = acc.y > 0.f ? acc.y : 0.f;
    out.z = acc.z > 0.f ? acc.z : 0.f;
    out.w = acc.w > 0.f ? acc.w : 0.f;
    *(float4*)(h + n * 64 + og * 4) = out;
}

// final epilogue: out = log_softmax(msg + x@root + bias); re-zero msg slice
__global__ void k_rootlsm(const float* __restrict__ x, const float* __restrict__ root,
                          const float* __restrict__ bias, float* __restrict__ out) {
    int n = blockIdx.x * blockDim.x + threadIdx.x;
    if (n >= N_NODES) return;
    float4 vlo = *(float4*)(d_msg + n * 8);
    float4 vhi = *(float4*)(d_msg + n * 8 + 4);
    float4 blo = __ldg((const float4*)bias);
    float4 bhi = __ldg((const float4*)bias + 1);
    vlo.x += blo.x; vlo.y += blo.y; vlo.z += blo.z; vlo.w += blo.w;
    vhi.x += bhi.x; vhi.y += bhi.y; vhi.z += bhi.z; vhi.w += bhi.w;
    *(float4*)(d_msg + n * 8) = make_float4(0.f, 0.f, 0.f, 0.f);
    *(float4*)(d_msg + n * 8 + 4) = make_float4(0.f, 0.f, 0.f, 0.f);
    const float4* x4 = (const float4*)(x + n * 64);
    const float4* r4 = (const float4*)root;   // [64][2] float4 view
#pragma unroll
    for (int i4 = 0; i4 < 16; i4++) {
        float4 xv = __ldg(&x4[i4]);
        float xs[4] = {xv.x, xv.y, xv.z, xv.w};
#pragma unroll
        for (int j = 0; j < 4; j++) {
            int i = i4 * 4 + j;
            float4 a = __ldg(&r4[i * 2]);
            float4 b = __ldg(&r4[i * 2 + 1]);
            vlo.x += xs[j] * a.x; vlo.y += xs[j] * a.y;
            vlo.z += xs[j] * a.z; vlo.w += xs[j] * a.w;
            vhi.x += xs[j] * b.x; vhi.y += xs[j] * b.y;
            vhi.z += xs[j] * b.z; vhi.w += xs[j] * b.w;
        }
    }
    float v[8] = {vlo.x, vlo.y, vlo.z, vlo.w, vhi.x, vhi.y, vhi.z, vhi.w};
    float m = -1e30f;
#pragma unroll
    for (int c = 0; c < 8; c++) m = fmaxf(m, v[c]);
    float s = 0.f;
#pragma unroll
    for (int c = 0; c < 8; c++) s += expf(v[c] - m);
    float ls = logf(s) + m;
#pragma unroll
    for (int c = 0; c < 8; c++) out[n * 8 + c] = v[c] - ls;
}

// ---------------- launch ----------------
extern "C" void kernel_launch(void* const* d_in, const int* in_sizes, int n_in,
                              void* d_out, int out_size) {
    const float* x0 = (const float*)d_in[0];
    const int* ei = (const int*)d_in[1];
    const int* et = (const int*)d_in[2];
    int E = in_sizes[2];
    const int* src = ei;
    const int* dst = ei + E;

    void *pA, *pB, *pW0, *pW1, *pW2;
    cudaGetSymbolAddress(&pA, d_hA);
    cudaGetSymbolAddress(&pB, d_hB);
    cudaGetSymbolAddress(&pW0, d_W0);
    cudaGetSymbolAddress(&pW1, d_W1);
    cudaGetSymbolAddress(&pW2, d_W2);
    float* hA = (float*)pA;
    float* hB = (float*)pB;

    const int SMEM64 = (128 * 68) * 4 + 129 * 4 + 128 * 4;
    const int SMEM8  = (64 * 8 + 128 * 68) * 4 + 129 * 4 + 128 * 4;
    cudaFuncSetAttribute(k_agg<64>, cudaFuncAttributeMaxDynamicSharedMemorySize, SMEM64);
    cudaFuncSetAttribute(k_agg<8>,  cudaFuncAttributeMaxDynamicSharedMemorySize, SMEM8);

    dim3 grid((N_NODES + 127) / 128, N_REL);

    // 1: prep;  2: scan;  3: compact+scatter+reset;  4: k_agg<64>  <- ncu slot
    k_prep<<<(E + 255) / 256, 256>>>(et, dst, E,
        (const float*)d_in[3], (const float*)d_in[4],
        (const float*)d_in[7], (const float*)d_in[8],
        (const float*)d_in[11], (const float*)d_in[12]);
    k_scan<<<NB2, 256>>>();
    k_cscat<<<(NSEG + 255) / 256, 256>>>(et, dst, src, E);

    k_agg<64><<<grid, 128, SMEM64>>>(x0, (const float*)pW0);
    k_rootrelu<<<(N_NODES * 16 + 255) / 256, 256>>>(x0, (const float*)d_in[5],
                                                    (const float*)d_in[6], hA);

    k_agg<64><<<grid, 128, SMEM64>>>(hA, (const float*)pW1);
    k_rootrelu<<<(N_NODES * 16 + 255) / 256, 256>>>(hA, (const float*)d_in[9],
                                                    (const float*)d_in[10], hB);

    k_agg<8><<<grid, 256, SMEM8>>>(hB, (const float*)pW2);
    k_rootlsm<<<(N_NODES + 255) / 256, 256>>>(hB, (const float*)d_in[13], (const float*)d_in[14],
                                              (float*)d_out);
}

// round 16
// speedup vs baseline: 1.5096x; 1.0629x over previous
#include <cuda_runtime.h>
#include <math.h>
#include <stdint.h>

// ---------------- problem constants ----------------
#define N_NODES 50000
#define N_REL   50
#define N_BASES 30
#define NSEG    (N_NODES * N_REL)
#define MAXE    1100000
#define SCAN_CHUNK 2048
#define NB2 ((NSEG + SCAN_CHUNK - 1) / SCAN_CHUNK)
#define FULLM 0xffffffffu
#define NBLK_MAX 8600

// ---------------- static device scratch (zero-initialized at load) ----------------
__device__ int d_cnt[NSEG];
__device__ int d_off[NSEG + 1];
__device__ int d_cpt[NSEG + 1];
__device__ int d_cur[NSEG];
__device__ int d_coff[MAXE + 2];
__device__ int d_cdst[MAXE];
__device__ int d_srcn[MAXE];
__device__ unsigned long long d_agg[NB2];
__device__ unsigned long long d_incl[NB2];
__device__ int d_stat[NB2];
__device__ int d_bidc;
__device__ int d_blkA[NBLK_MAX];   // compact-segment base of block
__device__ int d_blkB[NBLK_MAX];   // r | (nrows<<8)
__device__ int d_nblk;
__device__ float d_W0[N_REL * 64 * 64];   // fragment-order n=64 (see k_prep)
__device__ float d_W1[N_REL * 64 * 64];   // fragment-order n=64
__device__ float d_W2[N_REL * 64 * 8];    // fragment-order n=8
__device__ float d_msg[N_NODES * 64];
__device__ float d_hA[N_NODES * 64];
__device__ float d_hB[N_NODES * 64];

__device__ __forceinline__ float tf32r(float v) {
    uint32_t u;
    asm("cvt.rna.tf32.f32 %0, %1;" : "=r"(u) : "f"(v));
    return __uint_as_float(u);
}
__device__ __forceinline__ void red2(float* p, float a, float b) {
    asm volatile("red.global.add.v2.f32 [%0], {%1, %2};" :: "l"(p), "f"(a), "f"(b) : "memory");
}

// ---------------- fused prep: edge histogram + W precomputes ----------------
// W0/W1 in MMA B-fragment order (n=64):
//   fi in [0,4096): s=fi&3, lane=(fi>>2)&31, jp=(fi>>7)&3, kk=fi>>9
//   j=2*jp+(s>>1), hb=s&1, q=lane&3, g=lane>>2; k=kk*8+q+hb*4, o=j*8+g -> W[r][k][o]
// W2 in MMA B-fragment order (n=8):
//   fi in [0,512): s=fi&1, lane=(fi>>1)&31, kk=fi>>6
//   q=lane&3, g=lane>>2; k=kk*8+q+s*4, o=g -> W[r][k][o]
__global__ void k_prep(const int* __restrict__ et, const int* __restrict__ dst, int E,
                       const float* __restrict__ b0, const float* __restrict__ c0,
                       const float* __restrict__ b1, const float* __restrict__ c1,
                       const float* __restrict__ b2, const float* __restrict__ c2) {
    int i = blockIdx.x * blockDim.x + threadIdx.x;
    if (i < E) atomicAdd(&d_cnt[et[i] * N_NODES + dst[i]], 1);
    if (i < N_REL * 64 * 64) {
        int r = i >> 12, fi = i & 4095;
        int s = fi & 3, lane = (fi >> 2) & 31, jp = (fi >> 7) & 3, kk = fi >> 9;
        int j = 2 * jp + (s >> 1);
        int hb = s & 1;
        int q = lane & 3, g = lane >> 2;
        int k = kk * 8 + q + hb * 4;
        int o = j * 8 + g;
        int ko = k * 64 + o;
        float a0 = 0.f, a1 = 0.f;
#pragma unroll 6
        for (int b = 0; b < N_BASES; b++) {
            a0 += c0[r * N_BASES + b] * b0[b * 4096 + ko];
            a1 += c1[r * N_BASES + b] * b1[b * 4096 + ko];
        }
        d_W0[i] = tf32r(a0);
        d_W1[i] = tf32r(a1);
    }
    if (i < N_REL * 64 * 8) {
        int r = i >> 9, fi = i & 511;
        int s = fi & 1, lane = (fi >> 1) & 31, kk = fi >> 6;
        int q = lane & 3, g = lane >> 2;
        int ko = (kk * 8 + q + s * 4) * 8 + g;
        float a2 = 0.f;
#pragma unroll 6
        for (int b = 0; b < N_BASES; b++)
            a2 += c2[r * N_BASES + b] * b2[b * 512 + ko];
        d_W2[i] = tf32r(a2);
    }
}

// single-pass decoupled-lookback scan of (cnt, cnt>0)
__global__ void __launch_bounds__(256) k_scan() {
    __shared__ int sbid;
    __shared__ unsigned long long sexcl;
    __shared__ int ssum[256], sflg[256];
    int t = threadIdx.x;
    if (t == 0) sbid = atomicAdd(&d_bidc, 1);
    __syncthreads();
    int bid = sbid;
    int base = bid * SCAN_CHUNK + t * 8;
    int v[8], f[8];
    int run1 = 0, run2 = 0;
#pragma unroll
    for (int j = 0; j < 8; j++) {
        int idx = base + j;
        int c = (idx < NSEG) ? d_cnt[idx] : 0;
        v[j] = run1; f[j] = run2;
        run1 += c; run2 += (c > 0);
    }
    ssum[t] = run1; sflg[t] = run2;
    __syncthreads();
    for (int d = 1; d < 256; d <<= 1) {
        int a = 0, b = 0;
        if (t >= d) { a = ssum[t - d]; b = sflg[t - d]; }
        __syncthreads();
        if (t >= d) { ssum[t] += a; sflg[t] += b; }
        __syncthreads();
    }
    unsigned long long blockAgg =
        ((unsigned long long)(unsigned)ssum[255] << 32) | (unsigned)sflg[255];
    if (t == 0) {
        *((volatile unsigned long long*)&d_agg[bid]) = blockAgg;
        __threadfence();
        *((volatile int*)&d_stat[bid]) = 1;
    }
    if (t < 32) {
        unsigned long long excl = 0;
        int p = bid - 1;
        while (p >= 0) {
            int pi = p - t;
            int st;
            do {
                st = (pi >= 0) ? *((volatile int*)&d_stat[pi]) : 2;
            } while (__any_sync(FULLM, st == 0));
            unsigned m2 = __ballot_sync(FULLM, pi >= 0 && st == 2);
            if (m2) {
                int lead = __ffs(m2) - 1;
                unsigned long long vv = 0ull;
                if (pi >= 0) {
                    if (t < lead)       vv = *((volatile unsigned long long*)&d_agg[pi]);
                    else if (t == lead) vv = *((volatile unsigned long long*)&d_incl[pi]);
                }
                for (int o = 16; o > 0; o >>= 1) vv += __shfl_down_sync(FULLM, vv, o);
                excl += __shfl_sync(FULLM, vv, 0);
                break;
            } else {
                unsigned long long vv =
                    (pi >= 0) ? *((volatile unsigned long long*)&d_agg[pi]) : 0ull;
                for (int o = 16; o > 0; o >>= 1) vv += __shfl_down_sync(FULLM, vv, o);
                excl += __shfl_sync(FULLM, vv, 0);
                p -= 32;
            }
        }
        if (t == 0) {
            sexcl = excl;
            *((volatile unsigned long long*)&d_incl[bid]) = excl + blockAgg;
            __threadfence();
            *((volatile int*)&d_stat[bid]) = 2;
        }
    }
    __syncthreads();
    int exS = (int)(sexcl >> 32), exF = (int)(sexcl & 0xffffffffu);
    int ts = exS + ssum[t] - run1;
    int tf = exF + sflg[t] - run2;
#pragma unroll
    for (int j = 0; j < 8; j++) {
        int idx = base + j;
        if (idx < NSEG) {
            int o = ts + v[j];
            d_off[idx] = o; d_cur[idx] = o; d_cpt[idx] = tf + f[j];
        }
    }
    if (bid == NB2 - 1 && t == 255) {
        d_off[NSEG] = exS + ssum[255];
        d_cpt[NSEG] = exF + sflg[255];
    }
}

// compact CSR + counting-sort scatter + block-list build + state reset
__global__ void k_cscat(const int* __restrict__ et, const int* __restrict__ dst,
                        const int* __restrict__ src, int E) {
    int i = blockIdx.x * blockDim.x + threadIdx.x;
    int t = threadIdx.x;
    if (i < NSEG) {
        int c = d_cnt[i];
        if (c > 0) {
            int cc = d_cpt[i];
            d_coff[cc] = d_off[i];
            d_cdst[cc] = i % N_NODES;
        }
        d_cnt[i] = 0;
    }
    if (i < E) {
        int key = et[i] * N_NODES + dst[i];
        int p = atomicAdd(&d_cur[key], 1);
        d_srcn[p] = src[i];
    }
    if (i < NB2) d_stat[i] = 0;
    if (i == 0) {
        d_bidc = 0;
        d_coff[d_cpt[NSEG]] = E;
    }
    // block 0: build compact block list (d_cpt is ready after k_scan)
    if (blockIdx.x == 0) {
        __shared__ int snb[64];
        __shared__ int sbase[64];
        int nb = 0, cbase = 0;
        if (t < N_REL) {
            cbase = d_cpt[t * N_NODES];
            int m = d_cpt[(t + 1) * N_NODES] - cbase;
            nb = (m + 127) >> 7;
        }
        if (t < 64) snb[t] = nb;
        if (t < 64) sbase[t] = cbase;
        __syncthreads();
        // exclusive scan of snb over 64 entries (Hillis-Steele)
        __shared__ int spr[64];
        if (t < 64) spr[t] = snb[t];
        __syncthreads();
        for (int d = 1; d < 64; d <<= 1) {
            int a = 0;
            if (t < 64 && t >= d) a = spr[t - d];
            __syncthreads();
            if (t < 64 && t >= d) spr[t] += a;
            __syncthreads();
        }
        // spr is inclusive; exclusive = spr - snb
        if (t < N_REL) {
            int pref = spr[t] - snb[t];
            int m = d_cpt[(t + 1) * N_NODES] - sbase[t];
            for (int j = 0; j < nb; j++) {
                int nrows = m - j * 128;
                if (nrows > 128) nrows = 128;
                d_blkA[pref + j] = sbase[t] + j * 128;
                d_blkB[pref + j] = t | (nrows << 8);
            }
        }
        if (t == 0) d_nblk = spr[63];
    }
}

// ---------------- fused mean aggregation + tf32 MMA + red scatter ----------------
// 1D grid over compact block list. Block = up to 128 compact segments, one relation.
// DOUT==64: 128 threads / 4 warps; warp owns 32 rows = 2 MMA tiles (B reuse).
// DOUT==8:  256 threads / 8 warps; warp owns 16 rows = 1 tile; fragment-order W2
//   via LDG.64 (no Ws smem, no SIMT LDS storm).
template <int DOUT>
__global__ void __launch_bounds__(DOUT == 64 ? 128 : 256)
k_agg(const float* __restrict__ x, const float* __restrict__ W) {
    constexpr int NTH = (DOUT == 64) ? 128 : 256;
    extern __shared__ float smem[];
    float* As = smem;                   // [128][68]
    int* sso = (int*)(As + 128 * 68);   // [129]
    int* sdn = sso + 129;               // [128]

    int bid = blockIdx.x;
    if (bid >= d_nblk) return;
    int cb = d_blkA[bid];
    int rb = d_blkB[bid];
    int r = rb & 0xff;
    int nrows = rb >> 8;

    int t = threadIdx.x, lane = t & 31, w = t >> 5;

    // segment metadata
    for (int i = t; i < 129; i += NTH) sso[i] = d_coff[cb + min(i, nrows)];
    for (int i = t; i < 128; i += NTH) sdn[i] = (i < nrows) ? d_cdst[cb + i] : -1;
    __syncthreads();

    // ---- gather: 8 threads/segment, chunks of 4 unrolled passes ----
    {
        constexpr int SPP = NTH / 8;            // segments per pass
        constexpr int NCH = 128 / (4 * SPP);    // chunks
        int sub  = t & 7;
        int c0   = sub * 8;
        int segl = t >> 3;
#pragma unroll
        for (int ch = 0; ch < NCH; ch++) {
            int sb = ch * 4 * SPP;
            int e0[4], e1[4], s0[4];
#pragma unroll
            for (int p = 0; p < 4; p++) {
                int sg = sb + p * SPP + segl;
                e0[p] = sso[sg];
                e1[p] = sso[sg + 1];
            }
#pragma unroll
            for (int p = 0; p < 4; p++)
                s0[p] = (e1[p] > e0[p]) ? __ldg(&d_srcn[e0[p]]) : -1;
            float4 A0[4], A1[4];
#pragma unroll
            for (int p = 0; p < 4; p++) {
                if (s0[p] >= 0) {
                    const float4* xp = (const float4*)(x + s0[p] * 64 + c0);
                    A0[p] = __ldg(xp);
                    A1[p] = __ldg(xp + 1);
                } else {
                    A0[p] = make_float4(0.f, 0.f, 0.f, 0.f);
                    A1[p] = make_float4(0.f, 0.f, 0.f, 0.f);
                }
            }
#pragma unroll
            for (int p = 0; p < 4; p++) {
                for (int e = e0[p] + 1; e < e1[p]; e++) {
                    int s2 = __ldg(&d_srcn[e]);
                    const float4* xq = (const float4*)(x + s2 * 64 + c0);
                    float4 v0 = __ldg(xq), v1 = __ldg(xq + 1);
                    A0[p].x += v0.x; A0[p].y += v0.y; A0[p].z += v0.z; A0[p].w += v0.w;
                    A1[p].x += v1.x; A1[p].y += v1.y; A1[p].z += v1.z; A1[p].w += v1.w;
                }
            }
#pragma unroll
            for (int p = 0; p < 4; p++) {
                int cnt = e1[p] - e0[p];
                float inv = (cnt > 0) ? 1.f / (float)cnt : 0.f;
                int sg = sb + p * SPP + segl;
                float* dp = As + sg * 68 + c0;
                float4 o0, o1;
                o0.x = tf32r(A0[p].x * inv); o0.y = tf32r(A0[p].y * inv);
                o0.z = tf32r(A0[p].z * inv); o0.w = tf32r(A0[p].w * inv);
                o1.x = tf32r(A1[p].x * inv); o1.y = tf32r(A1[p].y * inv);
                o1.z = tf32r(A1[p].z * inv); o1.w = tf32r(A1[p].w * inv);
                *(float4*)dp = o0;
                *(float4*)(dp + 4) = o1;
            }
        }
    }
    __syncthreads();

    int g = lane >> 2, q = lane & 3;
    if (DOUT == 64) {
        const float* AL0 = As + (w * 32 + g) * 68;    // tile 0: rows g, g+8
        const float* AL8 = AL0 + 8 * 68;
        const float* AH0 = AL0 + 16 * 68;             // tile 1: rows g+16, g+24
        const float* AH8 = AL0 + 24 * 68;
        const float4* Wf = (const float4*)(W + r * 4096);
        float mac[2][8][4];
#pragma unroll
        for (int tt = 0; tt < 2; tt++)
#pragma unroll
            for (int j = 0; j < 8; j++)
#pragma unroll
                for (int i = 0; i < 4; i++) mac[tt][j][i] = 0.f;
#pragma unroll
        for (int kk = 0; kk < 8; kk++) {
            int k0 = kk * 8;
            uint32_t L0 = __float_as_uint(AL0[k0 + q]);
            uint32_t L1 = __float_as_uint(AL8[k0 + q]);
            uint32_t L2 = __float_as_uint(AL0[k0 + q + 4]);
            uint32_t L3 = __float_as_uint(AL8[k0 + q + 4]);
            uint32_t H0 = __float_as_uint(AH0[k0 + q]);
            uint32_t H1 = __float_as_uint(AH8[k0 + q]);
            uint32_t H2 = __float_as_uint(AH0[k0 + q + 4]);
            uint32_t H3 = __float_as_uint(AH8[k0 + q + 4]);
#pragma unroll
            for (int jp = 0; jp < 4; jp++) {
                float4 bf = __ldg(&Wf[(kk * 4 + jp) * 32 + lane]);
                uint32_t B0 = __float_as_uint(bf.x);
                uint32_t B1 = __float_as_uint(bf.y);
                uint32_t B2 = __float_as_uint(bf.z);
                uint32_t B3 = __float_as_uint(bf.w);
                asm volatile(
                    "mma.sync.aligned.m16n8k8.row.col.f32.tf32.tf32.f32 "
                    "{%0,%1,%2,%3}, {%4,%5,%6,%7}, {%8,%9}, {%0,%1,%2,%3};"
                    : "+f"(mac[0][2*jp][0]), "+f"(mac[0][2*jp][1]),
                      "+f"(mac[0][2*jp][2]), "+f"(mac[0][2*jp][3])
                    : "r"(L0), "r"(L1), "r"(L2), "r"(L3), "r"(B0), "r"(B1));
                asm volatile(
                    "mma.sync.aligned.m16n8k8.row.col.f32.tf32.tf32.f32 "
                    "{%0,%1,%2,%3}, {%4,%5,%6,%7}, {%8,%9}, {%0,%1,%2,%3};"
                    : "+f"(mac[0][2*jp+1][0]), "+f"(mac[0][2*jp+1][1]),
                      "+f"(mac[0][2*jp+1][2]), "+f"(mac[0][2*jp+1][3])
                    : "r"(L0), "r"(L1), "r"(L2), "r"(L3), "r"(B2), "r"(B3));
                asm volatile(
                    "mma.sync.aligned.m16n8k8.row.col.f32.tf32.tf32.f32 "
                    "{%0,%1,%2,%3}, {%4,%5,%6,%7}, {%8,%9}, {%0,%1,%2,%3};"
                    : "+f"(mac[1][2*jp][0]), "+f"(mac[1][2*jp][1]),
                      "+f"(mac[1][2*jp][2]), "+f"(mac[1][2*jp][3])
                    : "r"(H0), "r"(H1), "r"(H2), "r"(H3), "r"(B0), "r"(B1));
                asm volatile(
                    "mma.sync.aligned.m16n8k8.row.col.f32.tf32.tf32.f32 "
                    "{%0,%1,%2,%3}, {%4,%5,%6,%7}, {%8,%9}, {%0,%1,%2,%3};"
                    : "+f"(mac[1][2*jp+1][0]), "+f"(mac[1][2*jp+1][1]),
                      "+f"(mac[1][2*jp+1][2]), "+f"(mac[1][2*jp+1][3])
                    : "r"(H0), "r"(H1), "r"(H2), "r"(H3), "r"(B2), "r"(B3));
            }
        }
#pragma unroll
        for (int tt = 0; tt < 2; tt++) {
            int dA = sdn[w * 32 + tt * 16 + g];
            int dB = sdn[w * 32 + tt * 16 + 8 + g];
#pragma unroll
            for (int j = 0; j < 8; j++) {
                int col = j * 8 + 2 * q;
                if (dA >= 0) red2(&d_msg[dA * 64 + col], mac[tt][j][0], mac[tt][j][1]);
                if (dB >= 0) red2(&d_msg[dB * 64 + col], mac[tt][j][2], mac[tt][j][3]);
            }
        }
    } else {
        // DOUT == 8 : one 16x8 MMA tile per warp, fragment-order W2 via LDG.64
        const float* Ar0 = As + (w * 16 + g) * 68;
        const float* Ar8 = Ar0 + 8 * 68;
        const float2* Wf = (const float2*)(W + r * 512);
        float mac[4] = {0.f, 0.f, 0.f, 0.f};
#pragma unroll
        for (int kk = 0; kk < 8; kk++) {
            int k0 = kk * 8;
            uint32_t A0 = __float_as_uint(Ar0[k0 + q]);
            uint32_t A1 = __float_as_uint(Ar8[k0 + q]);
            uint32_t A2 = __float_as_uint(Ar0[k0 + q + 4]);
            uint32_t A3 = __float_as_uint(Ar8[k0 + q + 4]);
            float2 bf = __ldg(&Wf[kk * 32 + lane]);
            uint32_t B0 = __float_as_uint(bf.x);
            uint32_t B1 = __float_as_uint(bf.y);
            asm volatile(
                "mma.sync.aligned.m16n8k8.row.col.f32.tf32.tf32.f32 "
                "{%0,%1,%2,%3}, {%4,%5,%6,%7}, {%8,%9}, {%0,%1,%2,%3};"
                : "+f"(mac[0]), "+f"(mac[1]), "+f"(mac[2]), "+f"(mac[3])
                : "r"(A0), "r"(A1), "r"(A2), "r"(A3), "r"(B0), "r"(B1));
        }
        int dA = sdn[w * 16 + g];
        int dB = sdn[w * 16 + 8 + g];
        int col = 2 * q;
        if (dA >= 0) red2(&d_msg[dA * 8 + col], mac[0], mac[1]);
        if (dB >= 0) red2(&d_msg[dB * 8 + col], mac[2], mac[3]);
    }
}

// epilogue: h = relu(msg + x@root + bias); re-zero msg.
// Thread computes 4 consecutive outputs of one node; all loads float4.
__global__ void k_rootrelu(const float* __restrict__ x, const float* __restrict__ root,
                           const float* __restrict__ bias, float* __restrict__ h) {
    int idx = blockIdx.x * blockDim.x + threadIdx.x;
    if (idx >= N_NODES * 16) return;
    int n = idx >> 4, og = idx & 15;
    const float4* x4 = (const float4*)(x + n * 64);
    const float4* r4 = (const float4*)root;     // [64][16] float4 view
    float4 acc = __ldg((const float4*)bias + og);
    float4* mp = (float4*)(d_msg + n * 64 + og * 4);
    float4 m = *mp;
    acc.x += m.x; acc.y += m.y; acc.z += m.z; acc.w += m.w;
    *mp = make_float4(0.f, 0.f, 0.f, 0.f);
#pragma unroll
    for (int i4 = 0; i4 < 16; i4++) {
        float4 xv = __ldg(&x4[i4]);
        float4 r0 = __ldg(&r4[(i4 * 4 + 0) * 16 + og]);
        float4 r1 = __ldg(&r4[(i4 * 4 + 1) * 16 + og]);
        float4 r2 = __ldg(&r4[(i4 * 4 + 2) * 16 + og]);
        float4 r3 = __ldg(&r4[(i4 * 4 + 3) * 16 + og]);
        acc.x += xv.x * r0.x + xv.y * r1.x + xv.z * r2.x + xv.w * r3.x;
        acc.y += xv.x * r0.y + xv.y * r1.y + xv.z * r2.y + xv.w * r3.y;
        acc.z += xv.x * r0.z + xv.y * r1.z + xv.z * r2.z + xv.w * r3.z;
        acc.w += xv.x * r0.w + xv.y * r1.w + xv.z * r2.w + xv.w * r3.w;
    }
    float4 out;
    out.x = acc.x > 0.f ? acc.x : 0.f;
    out.y = acc.y > 0.f ? acc.y : 0.f;
    out.z = acc.z > 0.f ? acc.z : 0.f;
    out.w = acc.w > 0.f ? acc.w : 0.f;
    *(float4*)(h + n * 64 + og * 4) = out;
}

// final epilogue: out = log_softmax(msg + x@root + bias); re-zero msg slice
__global__ void k_rootlsm(const float* __restrict__ x, const float* __restrict__ root,
                          const float* __restrict__ bias, float* __restrict__ out) {
    int n = blockIdx.x * blockDim.x + threadIdx.x;
    if (n >= N_NODES) return;
    float4 vlo = *(float4*)(d_msg + n * 8);
    float4 vhi = *(float4*)(d_msg + n * 8 + 4);
    float4 blo = __ldg((const float4*)bias);
    float4 bhi = __ldg((const float4*)bias + 1);
    vlo.x += blo.x; vlo.y += blo.y; vlo.z += blo.z; vlo.w += blo.w;
    vhi.x += bhi.x; vhi.y += bhi.y; vhi.z += bhi.z; vhi.w += bhi.w;
    *(float4*)(d_msg + n * 8) = make_float4(0.f, 0.f, 0.f, 0.f);
    *(float4*)(d_msg + n * 8 + 4) = make_float4(0.f, 0.f, 0.f, 0.f);
    const float4* x4 = (const float4*)(x + n * 64);
    const float4* r4 = (const float4*)root;   // [64][2] float4 view
#pragma unroll
    for (int i4 = 0; i4 < 16; i4++) {
        float4 xv = __ldg(&x4[i4]);
        float xs[4] = {xv.x, xv.y, xv.z, xv.w};
#pragma unroll
        for (int j = 0; j < 4; j++) {
            int i = i4 * 4 + j;
            float4 a = __ldg(&r4[i * 2]);
            float4 b = __ldg(&r4[i * 2 + 1]);
            vlo.x += xs[j] * a.x; vlo.y += xs[j] * a.y;
            vlo.z += xs[j] * a.z; vlo.w += xs[j] * a.w;
            vhi.x += xs[j] * b.x; vhi.y += xs[j] * b.y;
            vhi.z += xs[j] * b.z; vhi.w += xs[j] * b.w;
        }
    }
    float v[8] = {vlo.x, vlo.y, vlo.z, vlo.w, vhi.x, vhi.y, vhi.z, vhi.w};
    float m = -1e30f;
#pragma unroll
    for (int c = 0; c < 8; c++) m = fmaxf(m, v[c]);
    float s = 0.f;
#pragma unroll
    for (int c = 0; c < 8; c++) s += expf(v[c] - m);
    float ls = logf(s) + m;
#pragma unroll
    for (int c = 0; c < 8; c++) out[n * 8 + c] = v[c] - ls;
}

// ---------------- launch ----------------
extern "C" void kernel_launch(void* const* d_in, const int* in_sizes, int n_in,
                              void* d_out, int out_size) {
    const float* x0 = (const float*)d_in[0];
    const int* ei = (const int*)d_in[1];
    const int* et = (const int*)d_in[2];
    int E = in_sizes[2];
    const int* src = ei;
    const int* dst = ei + E;

    void *pA, *pB, *pW0, *pW1, *pW2;
    cudaGetSymbolAddress(&pA, d_hA);
    cudaGetSymbolAddress(&pB, d_hB);
    cudaGetSymbolAddress(&pW0, d_W0);
    cudaGetSymbolAddress(&pW1, d_W1);
    cudaGetSymbolAddress(&pW2, d_W2);
    float* hA = (float*)pA;
    float* hB = (float*)pB;

    const int SMEM = (128 * 68) * 4 + 129 * 4 + 128 * 4;
    cudaFuncSetAttribute(k_agg<64>, cudaFuncAttributeMaxDynamicSharedMemorySize, SMEM);
    cudaFuncSetAttribute(k_agg<8>,  cudaFuncAttributeMaxDynamicSharedMemorySize, SMEM);

    // worst case blocks: E distinct segments -> ceil(E/128) + N_REL
    int nblk_ub = (E + 127) / 128 + N_REL;
    if (nblk_ub > NBLK_MAX) nblk_ub = NBLK_MAX;

    // 1: prep;  2: scan;  3: cscat(+blocklist+reset);  4: k_agg<64>  <- ncu slot
    k_prep<<<(E + 255) / 256, 256>>>(et, dst, E,
        (const float*)d_in[3], (const float*)d_in[4],
        (const float*)d_in[7], (const float*)d_in[8],
        (const float*)d_in[11], (const float*)d_in[12]);
    k_scan<<<NB2, 256>>>();
    k_cscat<<<(NSEG + 255) / 256, 256>>>(et, dst, src, E);

    k_agg<64><<<nblk_ub, 128, SMEM>>>(x0, (const float*)pW0);
    k_rootrelu<<<(N_NODES * 16 + 255) / 256, 256>>>(x0, (const float*)d_in[5],
                                                    (const float*)d_in[6], hA);

    k_agg<64><<<nblk_ub, 128, SMEM>>>(hA, (const float*)pW1);
    k_rootrelu<<<(N_NODES * 16 + 255) / 256, 256>>>(hA, (const float*)d_in[9],
                                                    (const float*)d_in[10], hB);

    k_agg<8><<<nblk_ub, 256, SMEM>>>(hB, (const float*)pW2);
    k_rootlsm<<<(N_NODES + 255) / 256, 256>>>(hB, (const float*)d_in[13], (const float*)d_in[14],
                                              (float*)d_out);
}

// round 17
// speedup vs baseline: 1.5715x; 1.0410x over previous
#include <cuda_runtime.h>
#include <math.h>
#include <stdint.h>

// ---------------- problem constants ----------------
#define N_NODES 50000
#define N_REL   50
#define N_BASES 30
#define NSEG    (N_NODES * N_REL)
#define MAXE    1100000
#define SCAN_CHUNK 2048
#define NB2 ((NSEG + SCAN_CHUNK - 1) / SCAN_CHUNK)
#define FULLM 0xffffffffu
#define NBLK_MAX 8600

// ---------------- static device scratch (zero-initialized at load) ----------------
__device__ int d_cnt[NSEG];
__device__ int d_off[NSEG + 1];
__device__ int d_cpt[NSEG + 1];
__device__ int d_cur[NSEG];
__device__ int d_coff[MAXE + 2];
__device__ int d_cdst[MAXE];
__device__ int d_srcn[MAXE];
__device__ unsigned long long d_agg[NB2];
__device__ unsigned long long d_incl[NB2];
__device__ int d_stat[NB2];
__device__ int d_bidc;
__device__ int d_blkA[NBLK_MAX];   // compact-segment base of block
__device__ int d_blkB[NBLK_MAX];   // r | (nrows<<8)
__device__ int d_nblk;
__device__ float d_W0[N_REL * 64 * 64];   // fragment-order n=64 (see k_prep)
__device__ float d_W1[N_REL * 64 * 64];   // fragment-order n=64
__device__ float d_W2[N_REL * 64 * 8];    // fragment-order n=8
__device__ float d_msg[N_NODES * 64];
__device__ float d_hA[N_NODES * 64];
__device__ float d_hB[N_NODES * 64];

__device__ __forceinline__ float tf32r(float v) {
    uint32_t u;
    asm("cvt.rna.tf32.f32 %0, %1;" : "=r"(u) : "f"(v));
    return __uint_as_float(u);
}
__device__ __forceinline__ void red2(float* p, float a, float b) {
    asm volatile("red.global.add.v2.f32 [%0], {%1, %2};" :: "l"(p), "f"(a), "f"(b) : "memory");
}

// ---------------- fused prep: edge histogram + W precomputes ----------------
// W0/W1 in MMA B-fragment order (n=64):
//   fi in [0,4096): s=fi&3, lane=(fi>>2)&31, jp=(fi>>7)&3, kk=fi>>9
//   j=2*jp+(s>>1), hb=s&1, q=lane&3, g=lane>>2; k=kk*8+q+hb*4, o=j*8+g -> W[r][k][o]
// W2 in MMA B-fragment order (n=8):
//   fi in [0,512): s=fi&1, lane=(fi>>1)&31, kk=fi>>6
//   q=lane&3, g=lane>>2; k=kk*8+q+s*4, o=g -> W[r][k][o]
__global__ void k_prep(const int* __restrict__ et, const int* __restrict__ dst, int E,
                       const float* __restrict__ b0, const float* __restrict__ c0,
                       const float* __restrict__ b1, const float* __restrict__ c1,
                       const float* __restrict__ b2, const float* __restrict__ c2) {
    int i = blockIdx.x * blockDim.x + threadIdx.x;
    if (i < E) atomicAdd(&d_cnt[et[i] * N_NODES + dst[i]], 1);
    if (i < N_REL * 64 * 64) {
        int r = i >> 12, fi = i & 4095;
        int s = fi & 3, lane = (fi >> 2) & 31, jp = (fi >> 7) & 3, kk = fi >> 9;
        int j = 2 * jp + (s >> 1);
        int hb = s & 1;
        int q = lane & 3, g = lane >> 2;
        int k = kk * 8 + q + hb * 4;
        int o = j * 8 + g;
        int ko = k * 64 + o;
        float a0 = 0.f, a1 = 0.f;
#pragma unroll 6
        for (int b = 0; b < N_BASES; b++) {
            a0 += c0[r * N_BASES + b] * b0[b * 4096 + ko];
            a1 += c1[r * N_BASES + b] * b1[b * 4096 + ko];
        }
        d_W0[i] = tf32r(a0);
        d_W1[i] = tf32r(a1);
    }
    if (i < N_REL * 64 * 8) {
        int r = i >> 9, fi = i & 511;
        int s = fi & 1, lane = (fi >> 1) & 31, kk = fi >> 6;
        int q = lane & 3, g = lane >> 2;
        int ko = (kk * 8 + q + s * 4) * 8 + g;
        float a2 = 0.f;
#pragma unroll 6
        for (int b = 0; b < N_BASES; b++)
            a2 += c2[r * N_BASES + b] * b2[b * 512 + ko];
        d_W2[i] = tf32r(a2);
    }
}

// single-pass decoupled-lookback scan of (cnt, cnt>0)
__global__ void __launch_bounds__(256) k_scan() {
    __shared__ int sbid;
    __shared__ unsigned long long sexcl;
    __shared__ int ssum[256], sflg[256];
    int t = threadIdx.x;
    if (t == 0) sbid = atomicAdd(&d_bidc, 1);
    __syncthreads();
    int bid = sbid;
    int base = bid * SCAN_CHUNK + t * 8;
    int v[8], f[8];
    int run1 = 0, run2 = 0;
#pragma unroll
    for (int j = 0; j < 8; j++) {
        int idx = base + j;
        int c = (idx < NSEG) ? d_cnt[idx] : 0;
        v[j] = run1; f[j] = run2;
        run1 += c; run2 += (c > 0);
    }
    ssum[t] = run1; sflg[t] = run2;
    __syncthreads();
    for (int d = 1; d < 256; d <<= 1) {
        int a = 0, b = 0;
        if (t >= d) { a = ssum[t - d]; b = sflg[t - d]; }
        __syncthreads();
        if (t >= d) { ssum[t] += a; sflg[t] += b; }
        __syncthreads();
    }
    unsigned long long blockAgg =
        ((unsigned long long)(unsigned)ssum[255] << 32) | (unsigned)sflg[255];
    if (t == 0) {
        *((volatile unsigned long long*)&d_agg[bid]) = blockAgg;
        __threadfence();
        *((volatile int*)&d_stat[bid]) = 1;
    }
    if (t < 32) {
        unsigned long long excl = 0;
        int p = bid - 1;
        while (p >= 0) {
            int pi = p - t;
            int st;
            do {
                st = (pi >= 0) ? *((volatile int*)&d_stat[pi]) : 2;
            } while (__any_sync(FULLM, st == 0));
            unsigned m2 = __ballot_sync(FULLM, pi >= 0 && st == 2);
            if (m2) {
                int lead = __ffs(m2) - 1;
                unsigned long long vv = 0ull;
                if (pi >= 0) {
                    if (t < lead)       vv = *((volatile unsigned long long*)&d_agg[pi]);
                    else if (t == lead) vv = *((volatile unsigned long long*)&d_incl[pi]);
                }
                for (int o = 16; o > 0; o >>= 1) vv += __shfl_down_sync(FULLM, vv, o);
                excl += __shfl_sync(FULLM, vv, 0);
                break;
            } else {
                unsigned long long vv =
                    (pi >= 0) ? *((volatile unsigned long long*)&d_agg[pi]) : 0ull;
                for (int o = 16; o > 0; o >>= 1) vv += __shfl_down_sync(FULLM, vv, o);
                excl += __shfl_sync(FULLM, vv, 0);
                p -= 32;
            }
        }
        if (t == 0) {
            sexcl = excl;
            *((volatile unsigned long long*)&d_incl[bid]) = excl + blockAgg;
            __threadfence();
            *((volatile int*)&d_stat[bid]) = 2;
        }
    }
    __syncthreads();
    int exS = (int)(sexcl >> 32), exF = (int)(sexcl & 0xffffffffu);
    int ts = exS + ssum[t] - run1;
    int tf = exF + sflg[t] - run2;
#pragma unroll
    for (int j = 0; j < 8; j++) {
        int idx = base + j;
        if (idx < NSEG) {
            int o = ts + v[j];
            d_off[idx] = o; d_cur[idx] = o; d_cpt[idx] = tf + f[j];
        }
    }
    if (bid == NB2 - 1 && t == 255) {
        d_off[NSEG] = exS + ssum[255];
        d_cpt[NSEG] = exF + sflg[255];
    }
}

// compact CSR + counting-sort scatter + block-list build + state reset
__global__ void k_cscat(const int* __restrict__ et, const int* __restrict__ dst,
                        const int* __restrict__ src, int E) {
    int i = blockIdx.x * blockDim.x + threadIdx.x;
    int t = threadIdx.x;
    if (i < NSEG) {
        int c = d_cnt[i];
        if (c > 0) {
            int cc = d_cpt[i];
            d_coff[cc] = d_off[i];
            d_cdst[cc] = i % N_NODES;
        }
        d_cnt[i] = 0;
    }
    if (i < E) {
        int key = et[i] * N_NODES + dst[i];
        int p = atomicAdd(&d_cur[key], 1);
        d_srcn[p] = src[i];
    }
    if (i < NB2) d_stat[i] = 0;
    if (i == 0) {
        d_bidc = 0;
        d_coff[d_cpt[NSEG]] = E;
    }
    // block 0: build compact block list (d_cpt is ready after k_scan)
    if (blockIdx.x == 0) {
        __shared__ int snb[64];
        __shared__ int sbase[64];
        int nb = 0, cbase = 0;
        if (t < N_REL) {
            cbase = d_cpt[t * N_NODES];
            int m = d_cpt[(t + 1) * N_NODES] - cbase;
            nb = (m + 127) >> 7;
        }
        if (t < 64) snb[t] = nb;
        if (t < 64) sbase[t] = cbase;
        __syncthreads();
        __shared__ int spr[64];
        if (t < 64) spr[t] = snb[t];
        __syncthreads();
        for (int d = 1; d < 64; d <<= 1) {
            int a = 0;
            if (t < 64 && t >= d) a = spr[t - d];
            __syncthreads();
            if (t < 64 && t >= d) spr[t] += a;
            __syncthreads();
        }
        if (t < N_REL) {
            int pref = spr[t] - snb[t];
            int m = d_cpt[(t + 1) * N_NODES] - sbase[t];
            for (int j = 0; j < nb; j++) {
                int nrows = m - j * 128;
                if (nrows > 128) nrows = 128;
                d_blkA[pref + j] = sbase[t] + j * 128;
                d_blkB[pref + j] = t | (nrows << 8);
            }
        }
        if (t == 0) d_nblk = spr[63];
    }
}

// ---------------- fused mean aggregation + tf32 MMA + red scatter ----------------
// 1D grid over compact block list. Block = up to 128 compact segments, one relation.
// DOUT==64: 128 threads / 4 warps; warp owns 32 rows = 2 MMA tiles with B reuse.
//   MMA epilogue runs in TWO column-half passes (jp 0-1 then 2-3): halves the live
//   accumulator count (64 -> 32 regs) to raise occupancy; B traffic unchanged.
// DOUT==8:  256 threads / 8 warps; warp owns 16 rows = 1 tile; fragment-order W2.
template <int DOUT>
__global__ void __launch_bounds__(DOUT == 64 ? 128 : 256)
k_agg(const float* __restrict__ x, const float* __restrict__ W) {
    constexpr int NTH = (DOUT == 64) ? 128 : 256;
    extern __shared__ float smem[];
    float* As = smem;                   // [128][68]
    int* sso = (int*)(As + 128 * 68);   // [129]
    int* sdn = sso + 129;               // [128]

    int bid = blockIdx.x;
    if (bid >= d_nblk) return;
    int cb = d_blkA[bid];
    int rb = d_blkB[bid];
    int r = rb & 0xff;
    int nrows = rb >> 8;

    int t = threadIdx.x, lane = t & 31, w = t >> 5;

    // segment metadata
    for (int i = t; i < 129; i += NTH) sso[i] = d_coff[cb + min(i, nrows)];
    for (int i = t; i < 128; i += NTH) sdn[i] = (i < nrows) ? d_cdst[cb + i] : -1;
    __syncthreads();

    // ---- gather: 8 threads/segment, chunks of 4 unrolled passes ----
    {
        constexpr int SPP = NTH / 8;            // segments per pass
        constexpr int NCH = 128 / (4 * SPP);    // chunks
        int sub  = t & 7;
        int c0   = sub * 8;
        int segl = t >> 3;
#pragma unroll
        for (int ch = 0; ch < NCH; ch++) {
            int sb = ch * 4 * SPP;
            int e0[4], e1[4], s0[4];
#pragma unroll
            for (int p = 0; p < 4; p++) {
                int sg = sb + p * SPP + segl;
                e0[p] = sso[sg];
                e1[p] = sso[sg + 1];
            }
#pragma unroll
            for (int p = 0; p < 4; p++)
                s0[p] = (e1[p] > e0[p]) ? __ldg(&d_srcn[e0[p]]) : -1;
            float4 A0[4], A1[4];
#pragma unroll
            for (int p = 0; p < 4; p++) {
                if (s0[p] >= 0) {
                    const float4* xp = (const float4*)(x + s0[p] * 64 + c0);
                    A0[p] = __ldg(xp);
                    A1[p] = __ldg(xp + 1);
                } else {
                    A0[p] = make_float4(0.f, 0.f, 0.f, 0.f);
                    A1[p] = make_float4(0.f, 0.f, 0.f, 0.f);
                }
            }
#pragma unroll
            for (int p = 0; p < 4; p++) {
                for (int e = e0[p] + 1; e < e1[p]; e++) {
                    int s2 = __ldg(&d_srcn[e]);
                    const float4* xq = (const float4*)(x + s2 * 64 + c0);
                    float4 v0 = __ldg(xq), v1 = __ldg(xq + 1);
                    A0[p].x += v0.x; A0[p].y += v0.y; A0[p].z += v0.z; A0[p].w += v0.w;
                    A1[p].x += v1.x; A1[p].y += v1.y; A1[p].z += v1.z; A1[p].w += v1.w;
                }
            }
#pragma unroll
            for (int p = 0; p < 4; p++) {
                int cnt = e1[p] - e0[p];
                float inv = (cnt > 0) ? 1.f / (float)cnt : 0.f;
                int sg = sb + p * SPP + segl;
                float* dp = As + sg * 68 + c0;
                float4 o0, o1;
                o0.x = tf32r(A0[p].x * inv); o0.y = tf32r(A0[p].y * inv);
                o0.z = tf32r(A0[p].z * inv); o0.w = tf32r(A0[p].w * inv);
                o1.x = tf32r(A1[p].x * inv); o1.y = tf32r(A1[p].y * inv);
                o1.z = tf32r(A1[p].z * inv); o1.w = tf32r(A1[p].w * inv);
                *(float4*)dp = o0;
                *(float4*)(dp + 4) = o1;
            }
        }
    }
    __syncthreads();

    int g = lane >> 2, q = lane & 3;
    if (DOUT == 64) {
        const float* AL0 = As + (w * 32 + g) * 68;    // tile 0: rows g, g+8
        const float* AL8 = AL0 + 8 * 68;
        const float* AH0 = AL0 + 16 * 68;             // tile 1: rows g+16, g+24
        const float* AH8 = AL0 + 24 * 68;
        const float4* Wf = (const float4*)(W + r * 4096);
        int dA0 = sdn[w * 32 + g];
        int dB0 = sdn[w * 32 + 8 + g];
        int dA1 = sdn[w * 32 + 16 + g];
        int dB1 = sdn[w * 32 + 24 + g];
#pragma unroll
        for (int half = 0; half < 2; half++) {
            float mac[2][4][4];
#pragma unroll
            for (int tt = 0; tt < 2; tt++)
#pragma unroll
                for (int j = 0; j < 4; j++)
#pragma unroll
                    for (int i = 0; i < 4; i++) mac[tt][j][i] = 0.f;
#pragma unroll
            for (int kk = 0; kk < 8; kk++) {
                int k0 = kk * 8;
                uint32_t L0 = __float_as_uint(AL0[k0 + q]);
                uint32_t L1 = __float_as_uint(AL8[k0 + q]);
                uint32_t L2 = __float_as_uint(AL0[k0 + q + 4]);
                uint32_t L3 = __float_as_uint(AL8[k0 + q + 4]);
                uint32_t H0 = __float_as_uint(AH0[k0 + q]);
                uint32_t H1 = __float_as_uint(AH8[k0 + q]);
                uint32_t H2 = __float_as_uint(AH0[k0 + q + 4]);
                uint32_t H3 = __float_as_uint(AH8[k0 + q + 4]);
#pragma unroll
                for (int jh = 0; jh < 2; jh++) {
                    int jp = half * 2 + jh;
                    float4 bf = __ldg(&Wf[(kk * 4 + jp) * 32 + lane]);
                    uint32_t B0 = __float_as_uint(bf.x);
                    uint32_t B1 = __float_as_uint(bf.y);
                    uint32_t B2 = __float_as_uint(bf.z);
                    uint32_t B3 = __float_as_uint(bf.w);
                    asm volatile(
                        "mma.sync.aligned.m16n8k8.row.col.f32.tf32.tf32.f32 "
                        "{%0,%1,%2,%3}, {%4,%5,%6,%7}, {%8,%9}, {%0,%1,%2,%3};"
                        : "+f"(mac[0][2*jh][0]), "+f"(mac[0][2*jh][1]),
                          "+f"(mac[0][2*jh][2]), "+f"(mac[0][2*jh][3])
                        : "r"(L0), "r"(L1), "r"(L2), "r"(L3), "r"(B0), "r"(B1));
                    asm volatile(
                        "mma.sync.aligned.m16n8k8.row.col.f32.tf32.tf32.f32 "
                        "{%0,%1,%2,%3}, {%4,%5,%6,%7}, {%8,%9}, {%0,%1,%2,%3};"
                        : "+f"(mac[0][2*jh+1][0]), "+f"(mac[0][2*jh+1][1]),
                          "+f"(mac[0][2*jh+1][2]), "+f"(mac[0][2*jh+1][3])
                        : "r"(L0), "r"(L1), "r"(L2), "r"(L3), "r"(B2), "r"(B3));
                    asm volatile(
                        "mma.sync.aligned.m16n8k8.row.col.f32.tf32.tf32.f32 "
                        "{%0,%1,%2,%3}, {%4,%5,%6,%7}, {%8,%9}, {%0,%1,%2,%3};"
                        : "+f"(mac[1][2*jh][0]), "+f"(mac[1][2*jh][1]),
                          "+f"(mac[1][2*jh][2]), "+f"(mac[1][2*jh][3])
                        : "r"(H0), "r"(H1), "r"(H2), "r"(H3), "r"(B0), "r"(B1));
                    asm volatile(
                        "mma.sync.aligned.m16n8k8.row.col.f32.tf32.tf32.f32 "
                        "{%0,%1,%2,%3}, {%4,%5,%6,%7}, {%8,%9}, {%0,%1,%2,%3};"
                        : "+f"(mac[1][2*jh+1][0]), "+f"(mac[1][2*jh+1][1]),
                          "+f"(mac[1][2*jh+1][2]), "+f"(mac[1][2*jh+1][3])
                        : "r"(H0), "r"(H1), "r"(H2), "r"(H3), "r"(B2), "r"(B3));
                }
            }
            int colb = half * 32 + 2 * q;
#pragma unroll
            for (int j = 0; j < 4; j++) {
                int col = colb + j * 8;
                if (dA0 >= 0) red2(&d_msg[dA0 * 64 + col], mac[0][j][0], mac[0][j][1]);
                if (dB0 >= 0) red2(&d_msg[dB0 * 64 + col], mac[0][j][2], mac[0][j][3]);
                if (dA1 >= 0) red2(&d_msg[dA1 * 64 + col], mac[1][j][0], mac[1][j][1]);
                if (dB1 >= 0) red2(&d_msg[dB1 * 64 + col], mac[1][j][2], mac[1][j][3]);
            }
        }
    } else {
        // DOUT == 8 : one 16x8 MMA tile per warp, fragment-order W2 via LDG.64
        const float* Ar0 = As + (w * 16 + g) * 68;
        const float* Ar8 = Ar0 + 8 * 68;
        const float2* Wf = (const float2*)(W + r * 512);
        float mac[4] = {0.f, 0.f, 0.f, 0.f};
#pragma unroll
        for (int kk = 0; kk < 8; kk++) {
            int k0 = kk * 8;
            uint32_t A0 = __float_as_uint(Ar0[k0 + q]);
            uint32_t A1 = __float_as_uint(Ar8[k0 + q]);
            uint32_t A2 = __float_as_uint(Ar0[k0 + q + 4]);
            uint32_t A3 = __float_as_uint(Ar8[k0 + q + 4]);
            float2 bf = __ldg(&Wf[kk * 32 + lane]);
            uint32_t B0 = __float_as_uint(bf.x);
            uint32_t B1 = __float_as_uint(bf.y);
            asm volatile(
                "mma.sync.aligned.m16n8k8.row.col.f32.tf32.tf32.f32 "
                "{%0,%1,%2,%3}, {%4,%5,%6,%7}, {%8,%9}, {%0,%1,%2,%3};"
                : "+f"(mac[0]), "+f"(mac[1]), "+f"(mac[2]), "+f"(mac[3])
                : "r"(A0), "r"(A1), "r"(A2), "r"(A3), "r"(B0), "r"(B1));
        }
        int dA = sdn[w * 16 + g];
        int dB = sdn[w * 16 + 8 + g];
        int col = 2 * q;
        if (dA >= 0) red2(&d_msg[dA * 8 + col], mac[0], mac[1]);
        if (dB >= 0) red2(&d_msg[dB * 8 + col], mac[2], mac[3]);
    }
}

// epilogue: h = relu(msg + x@root + bias); re-zero msg.
// Thread computes 4 consecutive outputs of one node; all loads float4.
__global__ void k_rootrelu(const float* __restrict__ x, const float* __restrict__ root,
                           const float* __restrict__ bias, float* __restrict__ h) {
    int idx = blockIdx.x * blockDim.x + threadIdx.x;
    if (idx >= N_NODES * 16) return;
    int n = idx >> 4, og = idx & 15;
    const float4* x4 = (const float4*)(x + n * 64);
    const float4* r4 = (const float4*)root;     // [64][16] float4 view
    float4 acc = __ldg((const float4*)bias + og);
    float4* mp = (float4*)(d_msg + n * 64 + og * 4);
    float4 m = *mp;
    acc.x += m.x; acc.y += m.y; acc.z += m.z; acc.w += m.w;
    *mp = make_float4(0.f, 0.f, 0.f, 0.f);
#pragma unroll
    for (int i4 = 0; i4 < 16; i4++) {
        float4 xv = __ldg(&x4[i4]);
        float4 r0 = __ldg(&r4[(i4 * 4 + 0) * 16 + og]);
        float4 r1 = __ldg(&r4[(i4 * 4 + 1) * 16 + og]);
        float4 r2 = __ldg(&r4[(i4 * 4 + 2) * 16 + og]);
        float4 r3 = __ldg(&r4[(i4 * 4 + 3) * 16 + og]);
        acc.x += xv.x * r0.x + xv.y * r1.x + xv.z * r2.x + xv.w * r3.x;
        acc.y += xv.x * r0.y + xv.y * r1.y + xv.z * r2.y + xv.w * r3.y;
        acc.z += xv.x * r0.z + xv.y * r1.z + xv.z * r2.z + xv.w * r3.z;
        acc.w += xv.x * r0.w + xv.y * r1.w + xv.z * r2.w + xv.w * r3.w;
    }
    float4 out;
    out.x = acc.x > 0.f ? acc.x : 0.f;
    out.y = acc.y > 0.f ? acc.y : 0.f;
    out.z = acc.z > 0.f ? acc.z : 0.f;
    out.w = acc.w > 0.f ? acc.w : 0.f;
    *(float4*)(h + n * 64 + og * 4) = out;
}

// final epilogue: out = log_softmax(msg + x@root + bias); re-zero msg slice
__global__ void k_rootlsm(const float* __restrict__ x, const float* __restrict__ root,
                          const float* __restrict__ bias, float* __restrict__ out) {
    int n = blockIdx.x * blockDim.x + threadIdx.x;
    if (n >= N_NODES) return;
    float4 vlo = *(float4*)(d_msg + n * 8);
    float4 vhi = *(float4*)(d_msg + n * 8 + 4);
    float4 blo = __ldg((const float4*)bias);
    float4 bhi = __ldg((const float4*)bias + 1);
    vlo.x += blo.x; vlo.y += blo.y; vlo.z += blo.z; vlo.w += blo.w;
    vhi.x += bhi.x; vhi.y += bhi.y; vhi.z += bhi.z; vhi.w += bhi.w;
    *(float4*)(d_msg + n * 8) = make_float4(0.f, 0.f, 0.f, 0.f);
    *(float4*)(d_msg + n * 8 + 4) = make_float4(0.f, 0.f, 0.f, 0.f);
    const float4* x4 = (const float4*)(x + n * 64);
    const float4* r4 = (const float4*)root;   // [64][2] float4 view
#pragma unroll
    for (int i4 = 0; i4 < 16; i4++) {
        float4 xv = __ldg(&x4[i4]);
        float xs[4] = {xv.x, xv.y, xv.z, xv.w};
#pragma unroll
        for (int j = 0; j < 4; j++) {
            int i = i4 * 4 + j;
            float4 a = __ldg(&r4[i * 2]);
            float4 b = __ldg(&r4[i * 2 + 1]);
            vlo.x += xs[j] * a.x; vlo.y += xs[j] * a.y;
            vlo.z += xs[j] * a.z; vlo.w += xs[j] * a.w;
            vhi.x += xs[j] * b.x; vhi.y += xs[j] * b.y;
            vhi.z += xs[j] * b.z; vhi.w += xs[j] * b.w;
        }
    }
    float v[8] = {vlo.x, vlo.y, vlo.z, vlo.w, vhi.x, vhi.y, vhi.z, vhi.w};
    float m = -1e30f;
#pragma unroll
    for (int c = 0; c < 8; c++) m = fmaxf(m, v[c]);
    float s = 0.f;
#pragma unroll
    for (int c = 0; c < 8; c++) s += expf(v[c] - m);
    float ls = logf(s) + m;
#pragma unroll
    for (int c = 0; c < 8; c++) out[n * 8 + c] = v[c] - ls;
}

// ---------------- launch ----------------
extern "C" void kernel_launch(void* const* d_in, const int* in_sizes, int n_in,
                              void* d_out, int out_size) {
    const float* x0 = (const float*)d_in[0];
    const int* ei = (const int*)d_in[1];
    const int* et = (const int*)d_in[2];
    int E = in_sizes[2];
    const int* src = ei;
    const int* dst = ei + E;

    void *pA, *pB, *pW0, *pW1, *pW2;
    cudaGetSymbolAddress(&pA, d_hA);
    cudaGetSymbolAddress(&pB, d_hB);
    cudaGetSymbolAddress(&pW0, d_W0);
    cudaGetSymbolAddress(&pW1, d_W1);
    cudaGetSymbolAddress(&pW2, d_W2);
    float* hA = (float*)pA;
    float* hB = (float*)pB;

    const int SMEM = (128 * 68) * 4 + 129 * 4 + 128 * 4;
    cudaFuncSetAttribute(k_agg<64>, cudaFuncAttributeMaxDynamicSharedMemorySize, SMEM);
    cudaFuncSetAttribute(k_agg<8>,  cudaFuncAttributeMaxDynamicSharedMemorySize, SMEM);

    int nblk_ub = (E + 127) / 128 + N_REL;
    if (nblk_ub > NBLK_MAX) nblk_ub = NBLK_MAX;

    // 1: prep;  2: scan;  3: cscat(+blocklist+reset);  4: k_agg<64>  <- ncu slot
    k_prep<<<(E + 255) / 256, 256>>>(et, dst, E,
        (const float*)d_in[3], (const float*)d_in[4],
        (const float*)d_in[7], (const float*)d_in[8],
        (const float*)d_in[11], (const float*)d_in[12]);
    k_scan<<<NB2, 256>>>();
    k_cscat<<<(NSEG + 255) / 256, 256>>>(et, dst, src, E);

    k_agg<64><<<nblk_ub, 128, SMEM>>>(x0, (const float*)pW0);
    k_rootrelu<<<(N_NODES * 16 + 255) / 256, 256>>>(x0, (const float*)d_in[5],
                                                    (const float*)d_in[6], hA);

    k_agg<64><<<nblk_ub, 128, SMEM>>>(hA, (const float*)pW1);
    k_rootrelu<<<(N_NODES * 16 + 255) / 256, 256>>>(hA, (const float*)d_in[9],
                                                    (const float*)d_in[10], hB);

    k_agg<8><<<nblk_ub, 256, SMEM>>>(hB, (const float*)pW2);
    k_rootlsm<<<(N_NODES + 255) / 256, 256>>>(hB, (const float*)d_in[13], (const float*)d_in[14],
                                              (float*)d_out);
}